// round 10
// baseline (speedup 1.0000x reference)
#include <cuda_runtime.h>
#include <cuda_fp16.h>
#include <cstdint>
#include <math.h>

#define BB 2
#define SS 2048
#define HH 1024
#define NHH 16
#define HDD 64
#define MM (BB*SS)   // 4096
#define HP (HH/2)    // 512 u32 per packed row

// ---------------- scratch (allocation-free: device globals) ----------------
__device__ uint32_t g_Hh [MM*HP];
__device__ uint32_t g_Wqh[HH*HP];
__device__ uint32_t g_Wkh[HH*HP];
__device__ uint32_t g_Wvh[HH*HP];
__device__ uint32_t g_Woh[HH*HP];
__device__ uint32_t g_AOh[MM*HP];
__device__ uint32_t g_Qh[BB*NHH*SS*(HDD/2)];
__device__ uint32_t g_Kh[BB*NHH*SS*(HDD/2)];
__device__ uint32_t g_Vt[BB*NHH*SS*(HDD/2)];
__device__ uint32_t g_Vh[BB*NHH*HDD*(SS/2)];
__device__ float2   g_tab[SS*32];

// ---------------- helpers ----------------------------------------------------
__device__ __forceinline__ uint32_t fpack(float a, float b) {
    __half2 h = __floats2half2_rn(a, b);
    return *reinterpret_cast<uint32_t*>(&h);
}

__device__ __forceinline__ void mma_fp16(float c[4], const uint32_t a[4], const uint32_t b[2]) {
    asm volatile(
        "mma.sync.aligned.m16n8k16.row.col.f32.f16.f16.f32 "
        "{%0,%1,%2,%3}, {%4,%5,%6,%7}, {%8,%9}, {%0,%1,%2,%3};"
        : "+f"(c[0]), "+f"(c[1]), "+f"(c[2]), "+f"(c[3])
        : "r"(a[0]), "r"(a[1]), "r"(a[2]), "r"(a[3]),
          "r"(b[0]), "r"(b[1]));
}

__device__ __forceinline__ uint32_t smem_u32(const void* p) {
    uint32_t a;
    asm("{ .reg .u64 t; cvta.to.shared.u64 t, %1; cvt.u32.u64 %0, t; }" : "=r"(a) : "l"(p));
    return a;
}

#define CPA16(dst, src) \
    asm volatile("cp.async.cg.shared.global [%0], [%1], 16;" :: "r"(dst), "l"(src))
#define CPA_COMMIT() asm volatile("cp.async.commit_group;" ::: "memory")
#define CPA_WAIT0()  asm volatile("cp.async.wait_group 0;" ::: "memory")
#define CPA_WAIT1()  asm volatile("cp.async.wait_group 1;" ::: "memory")

// ---------------- fused pack + rope table ------------------------------------
#define NHS (MM*HP)     // 2M u32
#define NWW (HH*HP)     // 512K u32
#define NTAB (SS*32)    // 64K
__global__ void __launch_bounds__(256) pack_all(const float* __restrict__ hs,
                                                const float* __restrict__ wq,
                                                const float* __restrict__ wk,
                                                const float* __restrict__ wv,
                                                const float* __restrict__ wo,
                                                uint32_t* __restrict__ Hh,
                                                uint32_t* __restrict__ Wqh,
                                                uint32_t* __restrict__ Wkh,
                                                uint32_t* __restrict__ Wvh,
                                                uint32_t* __restrict__ Woh,
                                                float2* __restrict__ tab)
{
    const int total = NTAB + NHS + 4 * NWW;
    int i = blockIdx.x * blockDim.x + threadIdx.x;
    const int stride = gridDim.x * blockDim.x;
    for (; i < total; i += stride) {
        if (i < NTAB) {
            const int p = i >> 5, fi = i & 31;
            const float inv = expf(-(float)fi * (logf(10000.0f) / 32.0f));
            float sn, cs;
            sincosf((float)p * inv, &sn, &cs);
            tab[i] = make_float2(cs, sn);
            continue;
        }
        const int t = i - NTAB;
        const float* s; uint32_t* d; int idx;
        if (t < NHS) { s = hs; d = Hh; idx = t; }
        else {
            const int j = t - NHS;
            const int wsel = j >> 19;
            idx = j & (NWW - 1);
            switch (wsel) {
                case 0: s = wq; d = Wqh; break;
                case 1: s = wk; d = Wkh; break;
                case 2: s = wv; d = Wvh; break;
                default: s = wo; d = Woh; break;
            }
        }
        float2 v = ((const float2*)s)[idx];
        d[idx] = fpack(v.x, v.y);
    }
}

// ---------------- GEMM v6: fp16, 128x128 CTA, warp tile 32x64, 3-stage ------
// 8 warps as 4(m) x 2(n). K-chunk 32 halves (16 u32). Single sync per iter.
// MODE 0: QKV fused (z: 0=Q RoPE+scale, 1=K RoPE, 2=V) -> packed fp16
// MODE 1: row-major fp32 [m*HH + o]
#define GTM 128
#define GTN 128
#define GSTR 20
#define GSTAGE ((GTM + GTN) * GSTR)     // 5120 u32
static const int GEMM_SMEM = 3 * GSTAGE * (int)sizeof(uint32_t);  // 61440

template<int MODE>
__global__ void __launch_bounds__(256, 2) gemm_v6(const uint32_t* __restrict__ A,
                                                  const uint32_t* __restrict__ B0,
                                                  const uint32_t* __restrict__ B1,
                                                  const uint32_t* __restrict__ B2,
                                                  void* __restrict__ Y0v,
                                                  void* __restrict__ Y1v,
                                                  void* __restrict__ Y2v,
                                                  const float2* __restrict__ tab,
                                                  const int* __restrict__ pos_ids)
{
    extern __shared__ uint32_t sm4[];
    const int z = blockIdx.z;
    const uint32_t* Bp = (z == 0) ? B0 : (z == 1) ? B1 : B2;
    void* Yv           = (z == 0) ? Y0v : (z == 1) ? Y1v : Y2v;

    const int tid  = threadIdx.x;
    const int w    = tid >> 5;
    const int lane = tid & 31;
    const int g    = lane >> 2;
    const int tg   = lane & 3;
    const int wm   = (w & 3) * 32;       // 4 m-warps
    const int wn   = (w >> 2) * 64;      // 2 n-warps
    const int m0   = blockIdx.y * GTM;
    const int n0   = blockIdx.x * GTN;
    const uint32_t sb = smem_u32(sm4);

    // 1024 16B-chunks per stage (256 rows x 4); 4 per thread
    #define ISSUE_G(IT, STG)                                                      \
        _Pragma("unroll")                                                         \
        for (int i = 0; i < 4; i++) {                                             \
            const int c = tid + i * 256;                                          \
            const int row = c >> 2, j = c & 3;                                    \
            const uint32_t* src = (row < GTM)                                     \
                ? A  + (size_t)(m0 + row)       * HP + (IT) * 16 + j * 4          \
                : Bp + (size_t)(n0 + row - GTM) * HP + (IT) * 16 + j * 4;         \
            CPA16(sb + ((STG) * GSTAGE + row * GSTR + j * 4) * 4, src);           \
        }

    ISSUE_G(0, 0); CPA_COMMIT();
    ISSUE_G(1, 1); CPA_COMMIT();

    float acc[2][8][4];
    #pragma unroll
    for (int mi = 0; mi < 2; mi++)
        #pragma unroll
        for (int ni = 0; ni < 8; ni++)
            #pragma unroll
            for (int r = 0; r < 4; r++) acc[mi][ni][r] = 0.f;

    const int NIT = HP / 16;             // 32
    #pragma unroll 1
    for (int it = 0; it < NIT; it++) {
        if (it < NIT - 1) { CPA_WAIT1(); } else { CPA_WAIT0(); }
        __syncthreads();                 // single sync per iter (3-stage ring)
        if (it + 2 < NIT) {
            ISSUE_G(it + 2, (it + 2) % 3);
            CPA_COMMIT();
        }

        const uint32_t* cS = sm4 + (it % 3) * GSTAGE;
        const uint32_t* cB = cS + GTM * GSTR;

        #pragma unroll
        for (int kk = 0; kk < 2; kk++) {
            const int kc = kk * 8;
            uint32_t a[2][4], b[8][2];
            #pragma unroll
            for (int mi = 0; mi < 2; mi++) {
                const int r0 = (wm + 16 * mi + g) * GSTR + kc;
                const int r8 = r0 + 8 * GSTR;
                a[mi][0] = cS[r0 + tg];
                a[mi][1] = cS[r8 + tg];
                a[mi][2] = cS[r0 + tg + 4];
                a[mi][3] = cS[r8 + tg + 4];
            }
            #pragma unroll
            for (int ni = 0; ni < 8; ni++) {
                const int rb = (wn + 8 * ni + g) * GSTR + kc;
                b[ni][0] = cB[rb + tg];
                b[ni][1] = cB[rb + tg + 4];
            }
            #pragma unroll
            for (int mi = 0; mi < 2; mi++)
                #pragma unroll
                for (int ni = 0; ni < 8; ni++)
                    mma_fp16(acc[mi][ni], a[mi], b[ni]);
        }
    }
    __syncthreads();   // protect smem reads of last iter (none follow, but cheap)

    if (MODE == 0) {
        uint32_t* Yh = (uint32_t*)Yv;
        const int nh = (n0 + wn) >> 6;
        const float qsc = (z == 0) ? 0.125f : 1.0f;
        #pragma unroll
        for (int mi = 0; mi < 2; mi++) {
            #pragma unroll
            for (int half = 0; half < 2; half++) {
                const int row = m0 + wm + 16 * mi + g + 8 * half;
                const int k0  = 2 * half;
                const int b_  = row >> 11;
                const int s   = row & (SS - 1);
                const size_t ob = ((size_t)(b_ * NHH + nh) * SS + s) * 32;
                if (z < 2) {
                    int p = pos_ids[b_ * SS + s];
                    p = min(max(p, 0), SS - 1);
                    const float2* tb = tab + p * 32;
                    #pragma unroll
                    for (int ni = 0; ni < 4; ni++) {
                        const int i0 = 8 * ni + 2 * tg;
                        const float2 t0 = tb[i0];
                        const float2 t1 = tb[i0 + 1];
                        const float lo0 = acc[mi][ni][k0],     lo1 = acc[mi][ni][k0 + 1];
                        const float hi0 = acc[mi][ni + 4][k0], hi1 = acc[mi][ni + 4][k0 + 1];
                        const float nl0 = (lo0 * t0.x - hi0 * t0.y) * qsc;
                        const float nl1 = (lo1 * t1.x - hi1 * t1.y) * qsc;
                        const float nh0 = (hi0 * t0.x + lo0 * t0.y) * qsc;
                        const float nh1 = (hi1 * t1.x + lo1 * t1.y) * qsc;
                        Yh[ob + 4 * ni + tg]      = fpack(nl0, nl1);
                        Yh[ob + 16 + 4 * ni + tg] = fpack(nh0, nh1);
                    }
                } else {
                    #pragma unroll
                    for (int ni = 0; ni < 8; ni++)
                        Yh[ob + 4 * ni + tg] = fpack(acc[mi][ni][k0], acc[mi][ni][k0 + 1]);
                }
            }
        }
    } else {
        float* Y = (float*)Yv;
        #pragma unroll
        for (int mi = 0; mi < 2; mi++) {
            #pragma unroll
            for (int ni = 0; ni < 8; ni++) {
                const int row = m0 + wm + 16 * mi + g;
                const int col = n0 + wn + 8 * ni + 2 * tg;
                *(float2*)&Y[(size_t)row * HH + col] =
                    make_float2(acc[mi][ni][0], acc[mi][ni][1]);
                *(float2*)&Y[(size_t)(row + 8) * HH + col] =
                    make_float2(acc[mi][ni][2], acc[mi][ni][3]);
            }
        }
    }
    #undef ISSUE_G
}

// ---------------- prep_v2: fp16 [bh][s][dp] -> fp16 [bh][d][sp] --------------
__global__ void __launch_bounds__(256) prep_v2(const uint32_t* __restrict__ Vt,
                                               uint32_t* __restrict__ Vh)
{
    __shared__ uint32_t vs[64 * 36];
    const int tid = threadIdx.x;
    const int bh  = blockIdx.y;
    const int st  = blockIdx.x * 64;
    const uint32_t* src = Vt + ((size_t)bh * SS + st) * 32;

    #pragma unroll
    for (int i = 0; i < 2; i++) {
        const int c = tid + i * 256;
        const int row = c >> 3, j = c & 7;
        uint4 v = *(const uint4*)&src[(size_t)row * 32 + j * 4];
        *(uint4*)&vs[row * 36 + j * 4] = v;
    }
    __syncthreads();

    const int d  = tid & 63;
    const int dp = d >> 1;
    const int sh = (d & 1) * 16;
    #pragma unroll
    for (int i = 0; i < 2; i++) {
        const int q = (tid >> 6) + i * 4;
        uint32_t o[4];
        #pragma unroll
        for (int k = 0; k < 4; k++) {
            const int sp = 4 * q + k;
            const uint32_t w0 = vs[(2 * sp) * 36 + dp];
            const uint32_t w1 = vs[(2 * sp + 1) * 36 + dp];
            o[k] = ((w0 >> sh) & 0xffffu) | (((w1 >> sh) & 0xffffu) << 16);
        }
        *(uint4*)&Vh[((size_t)bh * HDD + d) * (SS / 2) + (st >> 1) + 4 * q] =
            make_uint4(o[0], o[1], o[2], o[3]);
    }
}

// ---------------- flash attention: fp16 MMA, 3-stage cp.async, 1 sync/tile --
#define FQ 128
#define FK 64
#define HSTR 36
#define SQ_OFF 0
#define SK_OFF (FQ * HSTR)
#define STG_SZ (FK * HSTR * 2)          // 4608 u32 (K then V)
static const int FLASH_SMEM = (FQ * HSTR + 3 * STG_SZ) * (int)sizeof(uint32_t);  // 73728

__global__ void __launch_bounds__(256, 2) flash_fp16(const uint32_t* __restrict__ Qh,
                                                     const uint32_t* __restrict__ Kh,
                                                     const uint32_t* __restrict__ Vh,
                                                     uint32_t* __restrict__ AOh)
{
    extern __shared__ uint32_t fsm[];
    const uint32_t sb = smem_u32(fsm);

    const int tid  = threadIdx.x;
    const int w    = tid >> 5;
    const int lane = tid & 31;
    const int g    = lane >> 2;
    const int tg   = lane & 3;
    const int bh   = blockIdx.y;
    const int qt   = (int)(gridDim.x - 1) - (int)blockIdx.x;
    const int q0   = qt * FQ;

    const uint32_t* qsrc = Qh + ((size_t)bh * SS + q0) * 32;
    const uint32_t* ksrc = Kh + (size_t)bh * SS * 32;
    const uint32_t* vsrc = Vh + (size_t)bh * HDD * (SS / 2);

    const int nt = 2 * qt + 2;

    #define ISSUE_KV(KT, STG)                                                     \
        {                                                                         \
            _Pragma("unroll")                                                     \
            for (int i = 0; i < 2; i++) {                                         \
                const int c = tid + i * 256;                                      \
                const int row = c >> 3, j = c & 7;                                \
                CPA16(sb + (SK_OFF + (STG) * STG_SZ + row * HSTR + j * 4) * 4,    \
                      ksrc + ((size_t)(KT) * FK + row) * 32 + j * 4);             \
            }                                                                     \
            _Pragma("unroll")                                                     \
            for (int i = 0; i < 2; i++) {                                         \
                const int c = tid + i * 256;                                      \
                const int d = c >> 3, j = c & 7;                                  \
                CPA16(sb + (SK_OFF + (STG) * STG_SZ + FK * HSTR + d * HSTR + j * 4) * 4, \
                      vsrc + (size_t)d * (SS / 2) + (KT) * 32 + j * 4);           \
            }                                                                     \
        }

    #pragma unroll
    for (int i = 0; i < 4; i++) {
        const int c = tid + i * 256;
        const int row = c >> 3, j = c & 7;
        CPA16(sb + (SQ_OFF + row * HSTR + j * 4) * 4, qsrc + (size_t)row * 32 + j * 4);
    }
    ISSUE_KV(0, 0);
    CPA_COMMIT();
    if (nt > 1) { ISSUE_KV(1, 1); CPA_COMMIT(); }

    float m0r = -1e30f, m1r = -1e30f, l0 = 0.f, l1 = 0.f;
    float acc[8][4];
    #pragma unroll
    for (int ni = 0; ni < 8; ni++)
        #pragma unroll
        for (int r = 0; r < 4; r++) acc[ni][r] = 0.f;

    const int rloc0 = w * 16 + g;
    const int row0  = q0 + rloc0;
    const int row1  = row0 + 8;

    const uint32_t* Qs = fsm;

    #pragma unroll 1
    for (int kt = 0; kt < nt; kt++) {
        if (kt + 1 < nt) { CPA_WAIT1(); } else { CPA_WAIT0(); }
        __syncthreads();                 // single sync per tile (3-stage ring)
        if (kt + 2 < nt) { ISSUE_KV(kt + 2, (kt + 2) % 3); CPA_COMMIT(); }

        const uint32_t* Ks = fsm + SK_OFF + (kt % 3) * STG_SZ;
        const uint32_t* Vs = Ks + FK * HSTR;
        const int k0 = kt * FK;

        float sc[8][4];
        #pragma unroll
        for (int ni = 0; ni < 8; ni++)
            #pragma unroll
            for (int r = 0; r < 4; r++) sc[ni][r] = 0.f;

        #pragma unroll
        for (int kk = 0; kk < 4; kk++) {
            uint32_t a[4];
            const int r0b = rloc0 * HSTR + 8 * kk + tg;
            a[0] = Qs[r0b];
            a[1] = Qs[r0b + 8 * HSTR];
            a[2] = Qs[r0b + 4];
            a[3] = Qs[r0b + 8 * HSTR + 4];
            #pragma unroll
            for (int ni = 0; ni < 8; ni++) {
                uint32_t b[2];
                const int nb = (ni * 8 + g) * HSTR + 8 * kk + tg;
                b[0] = Ks[nb];
                b[1] = Ks[nb + 4];
                mma_fp16(sc[ni], a, b);
            }
        }

        if (kt >= 2 * qt) {
            #pragma unroll
            for (int ni = 0; ni < 8; ni++) {
                const int c = k0 + ni * 8 + 2 * tg;
                if (c     > row0) sc[ni][0] = -1e30f;
                if (c + 1 > row0) sc[ni][1] = -1e30f;
                if (c     > row1) sc[ni][2] = -1e30f;
                if (c + 1 > row1) sc[ni][3] = -1e30f;
            }
        }

        float mx0 = -1e30f, mx1 = -1e30f;
        #pragma unroll
        for (int ni = 0; ni < 8; ni++) {
            mx0 = fmaxf(mx0, fmaxf(sc[ni][0], sc[ni][1]));
            mx1 = fmaxf(mx1, fmaxf(sc[ni][2], sc[ni][3]));
        }
        #pragma unroll
        for (int off = 1; off < 4; off <<= 1) {
            mx0 = fmaxf(mx0, __shfl_xor_sync(0xffffffffu, mx0, off));
            mx1 = fmaxf(mx1, __shfl_xor_sync(0xffffffffu, mx1, off));
        }
        const float mn0 = fmaxf(m0r, mx0);
        const float mn1 = fmaxf(m1r, mx1);
        const float al0 = __expf(m0r - mn0);
        const float al1 = __expf(m1r - mn1);

        float s0 = 0.f, s1 = 0.f;
        #pragma unroll
        for (int ni = 0; ni < 8; ni++) {
            sc[ni][0] = __expf(sc[ni][0] - mn0);
            sc[ni][1] = __expf(sc[ni][1] - mn0);
            sc[ni][2] = __expf(sc[ni][2] - mn1);
            sc[ni][3] = __expf(sc[ni][3] - mn1);
            s0 += sc[ni][0] + sc[ni][1];
            s1 += sc[ni][2] + sc[ni][3];
        }
        #pragma unroll
        for (int off = 1; off < 4; off <<= 1) {
            s0 += __shfl_xor_sync(0xffffffffu, s0, off);
            s1 += __shfl_xor_sync(0xffffffffu, s1, off);
        }
        l0 = l0 * al0 + s0;
        l1 = l1 * al1 + s1;
        m0r = mn0; m1r = mn1;

        uint32_t ph[8][2];
        #pragma unroll
        for (int ni = 0; ni < 8; ni++) {
            acc[ni][0] *= al0; acc[ni][1] *= al0;
            acc[ni][2] *= al1; acc[ni][3] *= al1;
            ph[ni][0] = fpack(sc[ni][0], sc[ni][1]);
            ph[ni][1] = fpack(sc[ni][2], sc[ni][3]);
        }

        #pragma unroll
        for (int kk = 0; kk < 4; kk++) {
            uint32_t a[4];
            a[0] = ph[2 * kk][0];
            a[1] = ph[2 * kk][1];
            a[2] = ph[2 * kk + 1][0];
            a[3] = ph[2 * kk + 1][1];
            #pragma unroll
            for (int ni = 0; ni < 8; ni++) {
                uint32_t b[2];
                const int nb = (ni * 8 + g) * HSTR + 8 * kk + tg;
                b[0] = Vs[nb];
                b[1] = Vs[nb + 4];
                mma_fp16(acc[ni], a, b);
            }
        }
    }

    const float il0 = 1.f / l0;
    const float il1 = 1.f / l1;
    const int b_ = bh >> 4, nh = bh & 15;
    #pragma unroll
    for (int ni = 0; ni < 8; ni++) {
        const int cp = nh * 32 + ni * 4 + tg;
        AOh[(size_t)(b_ * SS + row0) * HP + cp] =
            fpack(acc[ni][0] * il0, acc[ni][1] * il0);
        AOh[(size_t)(b_ * SS + row1) * HP + cp] =
            fpack(acc[ni][2] * il1, acc[ni][3] * il1);
    }
    #undef ISSUE_KV
}

// ---------------- launcher ---------------------------------------------------
extern "C" void kernel_launch(void* const* d_in, const int* in_sizes, int n_in,
                              void* d_out, int out_size)
{
    (void)in_sizes; (void)n_in; (void)out_size;
    const float* hs = (const float*)d_in[0];
    const float* wq = (const float*)d_in[2];
    const float* wk = (const float*)d_in[3];
    const float* wv = (const float*)d_in[4];
    const float* wo = (const float*)d_in[5];
    const int*  pos = (const int*)d_in[6];
    float* out = (float*)d_out;

    uint32_t *Hh, *Wqh, *Wkh, *Wvh, *Woh, *AOh, *Qh, *Kh, *Vt, *Vh;
    float2* tab;
    cudaGetSymbolAddress((void**)&Hh,  g_Hh);
    cudaGetSymbolAddress((void**)&Wqh, g_Wqh);
    cudaGetSymbolAddress((void**)&Wkh, g_Wkh);
    cudaGetSymbolAddress((void**)&Wvh, g_Wvh);
    cudaGetSymbolAddress((void**)&Woh, g_Woh);
    cudaGetSymbolAddress((void**)&AOh, g_AOh);
    cudaGetSymbolAddress((void**)&Qh,  g_Qh);
    cudaGetSymbolAddress((void**)&Kh,  g_Kh);
    cudaGetSymbolAddress((void**)&Vt,  g_Vt);
    cudaGetSymbolAddress((void**)&Vh,  g_Vh);
    cudaGetSymbolAddress((void**)&tab, g_tab);

    static bool attr_done = false;
    if (!attr_done) {
        cudaFuncSetAttribute(gemm_v6<0>,
                             cudaFuncAttributeMaxDynamicSharedMemorySize, GEMM_SMEM);
        cudaFuncSetAttribute(gemm_v6<1>,
                             cudaFuncAttributeMaxDynamicSharedMemorySize, GEMM_SMEM);
        cudaFuncSetAttribute(flash_fp16,
                             cudaFuncAttributeMaxDynamicSharedMemorySize, FLASH_SMEM);
        attr_done = true;
    }

    pack_all<<<1024, 256>>>(hs, wq, wk, wv, wo, Hh, Wqh, Wkh, Wvh, Woh, tab);

    gemm_v6<0><<<dim3(HH/GTN, MM/GTM, 3), 256, GEMM_SMEM>>>(
        Hh, Wqh, Wkh, Wvh, Qh, Kh, Vt, tab, pos);

    prep_v2<<<dim3(SS/64, BB*NHH), 256>>>(Vt, Vh);

    flash_fp16<<<dim3(SS/FQ, BB*NHH), 256, FLASH_SMEM>>>(Qh, Kh, Vh, AOh);

    gemm_v6<1><<<dim3(HH/GTN, MM/GTM, 1), 256, GEMM_SMEM>>>(
        AOh, Woh, Woh, Woh, out, out, out, tab, pos);
}

// round 11
// speedup vs baseline: 1.1012x; 1.1012x over previous
#include <cuda_runtime.h>
#include <cuda_fp16.h>
#include <cstdint>
#include <math.h>

#define BB 2
#define SS 2048
#define HH 1024
#define NHH 16
#define HDD 64
#define MM (BB*SS)   // 4096
#define HP (HH/2)    // 512 u32 per packed row

// ---------------- scratch (allocation-free: device globals) ----------------
__device__ uint32_t g_Hh [MM*HP];
__device__ uint32_t g_Wqh[HH*HP];
__device__ uint32_t g_Wkh[HH*HP];
__device__ uint32_t g_Wvh[HH*HP];
__device__ uint32_t g_Woh[HH*HP];
__device__ uint32_t g_AOh[MM*HP];
__device__ uint32_t g_Qh[BB*NHH*SS*(HDD/2)];
__device__ uint32_t g_Kh[BB*NHH*SS*(HDD/2)];
__device__ uint32_t g_Vt[BB*NHH*SS*(HDD/2)];
__device__ uint32_t g_Vh[BB*NHH*HDD*(SS/2)];
__device__ float2   g_tab[SS*32];

// ---------------- helpers ----------------------------------------------------
__device__ __forceinline__ uint32_t fpack(float a, float b) {
    __half2 h = __floats2half2_rn(a, b);
    return *reinterpret_cast<uint32_t*>(&h);
}

__device__ __forceinline__ void mma_fp16(float c[4], const uint32_t a[4], const uint32_t b[2]) {
    asm volatile(
        "mma.sync.aligned.m16n8k16.row.col.f32.f16.f16.f32 "
        "{%0,%1,%2,%3}, {%4,%5,%6,%7}, {%8,%9}, {%0,%1,%2,%3};"
        : "+f"(c[0]), "+f"(c[1]), "+f"(c[2]), "+f"(c[3])
        : "r"(a[0]), "r"(a[1]), "r"(a[2]), "r"(a[3]),
          "r"(b[0]), "r"(b[1]));
}

__device__ __forceinline__ uint32_t smem_u32(const void* p) {
    uint32_t a;
    asm("{ .reg .u64 t; cvta.to.shared.u64 t, %1; cvt.u32.u64 %0, t; }" : "=r"(a) : "l"(p));
    return a;
}

#define CPA16(dst, src) \
    asm volatile("cp.async.cg.shared.global [%0], [%1], 16;" :: "r"(dst), "l"(src))
#define CPA_COMMIT() asm volatile("cp.async.commit_group;" ::: "memory")
#define CPA_WAIT0()  asm volatile("cp.async.wait_group 0;" ::: "memory")
#define CPA_WAIT1()  asm volatile("cp.async.wait_group 1;" ::: "memory")

#define LOG2E 1.4426950408889634f

// ---------------- fused pack + rope table ------------------------------------
#define NHS (MM*HP)
#define NWW (HH*HP)
#define NTAB (SS*32)
__global__ void __launch_bounds__(256) pack_all(const float* __restrict__ hs,
                                                const float* __restrict__ wq,
                                                const float* __restrict__ wk,
                                                const float* __restrict__ wv,
                                                const float* __restrict__ wo,
                                                uint32_t* __restrict__ Hh,
                                                uint32_t* __restrict__ Wqh,
                                                uint32_t* __restrict__ Wkh,
                                                uint32_t* __restrict__ Wvh,
                                                uint32_t* __restrict__ Woh,
                                                float2* __restrict__ tab)
{
    const int total = NTAB + NHS + 4 * NWW;
    int i = blockIdx.x * blockDim.x + threadIdx.x;
    const int stride = gridDim.x * blockDim.x;
    for (; i < total; i += stride) {
        if (i < NTAB) {
            const int p = i >> 5, fi = i & 31;
            const float inv = expf(-(float)fi * (logf(10000.0f) / 32.0f));
            float sn, cs;
            sincosf((float)p * inv, &sn, &cs);
            tab[i] = make_float2(cs, sn);
            continue;
        }
        const int t = i - NTAB;
        const float* s; uint32_t* d; int idx;
        if (t < NHS) { s = hs; d = Hh; idx = t; }
        else {
            const int j = t - NHS;
            const int wsel = j >> 19;
            idx = j & (NWW - 1);
            switch (wsel) {
                case 0: s = wq; d = Wqh; break;
                case 1: s = wk; d = Wkh; break;
                case 2: s = wv; d = Wvh; break;
                default: s = wo; d = Woh; break;
            }
        }
        float2 v = ((const float2*)s)[idx];
        d[idx] = fpack(v.x, v.y);
    }
}

// ---------------- GEMM v7: fp16, 128x128 CTA, K-chunk 64, 3-stage -----------
// 8 warps as 4(m) x 2(n), warp tile 32x64. 64 MMAs per warp per iter,
// one __syncthreads per 64 K-elems. Stage: 256 rows x 36 u32 (32 data + 4 pad).
#define GTM 128
#define GTN 128
#define GSTR 36
#define GSTAGE ((GTM + GTN) * GSTR)     // 9216 u32
static const int GEMM_SMEM = 3 * GSTAGE * (int)sizeof(uint32_t);  // 110592

template<int MODE>
__global__ void __launch_bounds__(256, 2) gemm_v7(const uint32_t* __restrict__ A,
                                                  const uint32_t* __restrict__ B0,
                                                  const uint32_t* __restrict__ B1,
                                                  const uint32_t* __restrict__ B2,
                                                  void* __restrict__ Y0v,
                                                  void* __restrict__ Y1v,
                                                  void* __restrict__ Y2v,
                                                  const float2* __restrict__ tab,
                                                  const int* __restrict__ pos_ids)
{
    extern __shared__ uint32_t sm4[];
    const int z = blockIdx.z;
    const uint32_t* Bp = (z == 0) ? B0 : (z == 1) ? B1 : B2;
    void* Yv           = (z == 0) ? Y0v : (z == 1) ? Y1v : Y2v;

    const int tid  = threadIdx.x;
    const int w    = tid >> 5;
    const int lane = tid & 31;
    const int g    = lane >> 2;
    const int tg   = lane & 3;
    const int wm   = (w & 3) * 32;
    const int wn   = (w >> 2) * 64;
    const int m0   = blockIdx.y * GTM;
    const int n0   = blockIdx.x * GTN;
    const uint32_t sb = smem_u32(sm4);

    // 2048 16B-chunks per stage (256 rows x 8); 8 per thread
    #define ISSUE_G(IT, STG)                                                      \
        _Pragma("unroll")                                                         \
        for (int i = 0; i < 8; i++) {                                             \
            const int c = tid + i * 256;                                          \
            const int row = c >> 3, j = c & 7;                                    \
            const uint32_t* src = (row < GTM)                                     \
                ? A  + (size_t)(m0 + row)       * HP + (IT) * 32 + j * 4          \
                : Bp + (size_t)(n0 + row - GTM) * HP + (IT) * 32 + j * 4;         \
            CPA16(sb + ((STG) * GSTAGE + row * GSTR + j * 4) * 4, src);           \
        }

    ISSUE_G(0, 0); CPA_COMMIT();
    ISSUE_G(1, 1); CPA_COMMIT();

    float acc[2][8][4];
    #pragma unroll
    for (int mi = 0; mi < 2; mi++)
        #pragma unroll
        for (int ni = 0; ni < 8; ni++)
            #pragma unroll
            for (int r = 0; r < 4; r++) acc[mi][ni][r] = 0.f;

    const int NIT = HP / 32;             // 16
    #pragma unroll 1
    for (int it = 0; it < NIT; it++) {
        if (it < NIT - 1) { CPA_WAIT1(); } else { CPA_WAIT0(); }
        __syncthreads();
        if (it + 2 < NIT) {
            ISSUE_G(it + 2, (it + 2) % 3);
            CPA_COMMIT();
        }

        const uint32_t* cS = sm4 + (it % 3) * GSTAGE;
        const uint32_t* cB = cS + GTM * GSTR;

        #pragma unroll
        for (int kk = 0; kk < 4; kk++) {
            const int kc = kk * 8;
            uint32_t a[2][4], b[8][2];
            #pragma unroll
            for (int mi = 0; mi < 2; mi++) {
                const int r0 = (wm + 16 * mi + g) * GSTR + kc;
                const int r8 = r0 + 8 * GSTR;
                a[mi][0] = cS[r0 + tg];
                a[mi][1] = cS[r8 + tg];
                a[mi][2] = cS[r0 + tg + 4];
                a[mi][3] = cS[r8 + tg + 4];
            }
            #pragma unroll
            for (int ni = 0; ni < 8; ni++) {
                const int rb = (wn + 8 * ni + g) * GSTR + kc;
                b[ni][0] = cB[rb + tg];
                b[ni][1] = cB[rb + tg + 4];
            }
            #pragma unroll
            for (int mi = 0; mi < 2; mi++)
                #pragma unroll
                for (int ni = 0; ni < 8; ni++)
                    mma_fp16(acc[mi][ni], a[mi], b[ni]);
        }
    }

    if (MODE == 0) {
        uint32_t* Yh = (uint32_t*)Yv;
        const int nh = (n0 + wn) >> 6;
        // fold 1/sqrt(HD) * log2(e) into Q so flash can use exp2
        const float qsc = (z == 0) ? (0.125f * LOG2E) : 1.0f;
        #pragma unroll
        for (int mi = 0; mi < 2; mi++) {
            #pragma unroll
            for (int half = 0; half < 2; half++) {
                const int row = m0 + wm + 16 * mi + g + 8 * half;
                const int k0  = 2 * half;
                const int b_  = row >> 11;
                const int s   = row & (SS - 1);
                const size_t ob = ((size_t)(b_ * NHH + nh) * SS + s) * 32;
                if (z < 2) {
                    int p = pos_ids[b_ * SS + s];
                    p = min(max(p, 0), SS - 1);
                    const float2* tb = tab + p * 32;
                    #pragma unroll
                    for (int ni = 0; ni < 4; ni++) {
                        const int i0 = 8 * ni + 2 * tg;
                        const float2 t0 = tb[i0];
                        const float2 t1 = tb[i0 + 1];
                        const float lo0 = acc[mi][ni][k0],     lo1 = acc[mi][ni][k0 + 1];
                        const float hi0 = acc[mi][ni + 4][k0], hi1 = acc[mi][ni + 4][k0 + 1];
                        const float nl0 = (lo0 * t0.x - hi0 * t0.y) * qsc;
                        const float nl1 = (lo1 * t1.x - hi1 * t1.y) * qsc;
                        const float nh0 = (hi0 * t0.x + lo0 * t0.y) * qsc;
                        const float nh1 = (hi1 * t1.x + lo1 * t1.y) * qsc;
                        Yh[ob + 4 * ni + tg]      = fpack(nl0, nl1);
                        Yh[ob + 16 + 4 * ni + tg] = fpack(nh0, nh1);
                    }
                } else {
                    #pragma unroll
                    for (int ni = 0; ni < 8; ni++)
                        Yh[ob + 4 * ni + tg] = fpack(acc[mi][ni][k0], acc[mi][ni][k0 + 1]);
                }
            }
        }
    } else {
        float* Y = (float*)Yv;
        #pragma unroll
        for (int mi = 0; mi < 2; mi++) {
            #pragma unroll
            for (int ni = 0; ni < 8; ni++) {
                const int row = m0 + wm + 16 * mi + g;
                const int col = n0 + wn + 8 * ni + 2 * tg;
                *(float2*)&Y[(size_t)row * HH + col] =
                    make_float2(acc[mi][ni][0], acc[mi][ni][1]);
                *(float2*)&Y[(size_t)(row + 8) * HH + col] =
                    make_float2(acc[mi][ni][2], acc[mi][ni][3]);
            }
        }
    }
    #undef ISSUE_G
}

// ---------------- prep_v2: fp16 [bh][s][dp] -> fp16 [bh][d][sp] --------------
__global__ void __launch_bounds__(256) prep_v2(const uint32_t* __restrict__ Vt,
                                               uint32_t* __restrict__ Vh)
{
    __shared__ uint32_t vs[64 * 36];
    const int tid = threadIdx.x;
    const int bh  = blockIdx.y;
    const int st  = blockIdx.x * 64;
    const uint32_t* src = Vt + ((size_t)bh * SS + st) * 32;

    #pragma unroll
    for (int i = 0; i < 2; i++) {
        const int c = tid + i * 256;
        const int row = c >> 3, j = c & 7;
        uint4 v = *(const uint4*)&src[(size_t)row * 32 + j * 4];
        *(uint4*)&vs[row * 36 + j * 4] = v;
    }
    __syncthreads();

    const int d  = tid & 63;
    const int dp = d >> 1;
    const int sh = (d & 1) * 16;
    #pragma unroll
    for (int i = 0; i < 2; i++) {
        const int q = (tid >> 6) + i * 4;
        uint32_t o[4];
        #pragma unroll
        for (int k = 0; k < 4; k++) {
            const int sp = 4 * q + k;
            const uint32_t w0 = vs[(2 * sp) * 36 + dp];
            const uint32_t w1 = vs[(2 * sp + 1) * 36 + dp];
            o[k] = ((w0 >> sh) & 0xffffu) | (((w1 >> sh) & 0xffffu) << 16);
        }
        *(uint4*)&Vh[((size_t)bh * HDD + d) * (SS / 2) + (st >> 1) + 4 * q] =
            make_uint4(o[0], o[1], o[2], o[3]);
    }
}

// ---------------- flash attention: fp16 MMA, base-2 softmax, 3-stage --------
#define FQ 128
#define FK 64
#define HSTR 36
#define SQ_OFF 0
#define SK_OFF (FQ * HSTR)
#define STG_SZ (FK * HSTR * 2)
static const int FLASH_SMEM = (FQ * HSTR + 3 * STG_SZ) * (int)sizeof(uint32_t);  // 73728

__global__ void __launch_bounds__(256, 2) flash_fp16(const uint32_t* __restrict__ Qh,
                                                     const uint32_t* __restrict__ Kh,
                                                     const uint32_t* __restrict__ Vh,
                                                     uint32_t* __restrict__ AOh)
{
    extern __shared__ uint32_t fsm[];
    const uint32_t sb = smem_u32(fsm);

    const int tid  = threadIdx.x;
    const int w    = tid >> 5;
    const int lane = tid & 31;
    const int g    = lane >> 2;
    const int tg   = lane & 3;
    const int bh   = blockIdx.y;
    const int qt   = (int)(gridDim.x - 1) - (int)blockIdx.x;
    const int q0   = qt * FQ;

    const uint32_t* qsrc = Qh + ((size_t)bh * SS + q0) * 32;
    const uint32_t* ksrc = Kh + (size_t)bh * SS * 32;
    const uint32_t* vsrc = Vh + (size_t)bh * HDD * (SS / 2);

    const int nt = 2 * qt + 2;

    #define ISSUE_KV(KT, STG)                                                     \
        {                                                                         \
            _Pragma("unroll")                                                     \
            for (int i = 0; i < 2; i++) {                                         \
                const int c = tid + i * 256;                                      \
                const int row = c >> 3, j = c & 7;                                \
                CPA16(sb + (SK_OFF + (STG) * STG_SZ + row * HSTR + j * 4) * 4,    \
                      ksrc + ((size_t)(KT) * FK + row) * 32 + j * 4);             \
            }                                                                     \
            _Pragma("unroll")                                                     \
            for (int i = 0; i < 2; i++) {                                         \
                const int c = tid + i * 256;                                      \
                const int d = c >> 3, j = c & 7;                                  \
                CPA16(sb + (SK_OFF + (STG) * STG_SZ + FK * HSTR + d * HSTR + j * 4) * 4, \
                      vsrc + (size_t)d * (SS / 2) + (KT) * 32 + j * 4);           \
            }                                                                     \
        }

    #pragma unroll
    for (int i = 0; i < 4; i++) {
        const int c = tid + i * 256;
        const int row = c >> 3, j = c & 7;
        CPA16(sb + (SQ_OFF + row * HSTR + j * 4) * 4, qsrc + (size_t)row * 32 + j * 4);
    }
    ISSUE_KV(0, 0);
    CPA_COMMIT();
    if (nt > 1) { ISSUE_KV(1, 1); CPA_COMMIT(); }

    float m0r = -1e30f, m1r = -1e30f, l0 = 0.f, l1 = 0.f;
    float acc[8][4];
    #pragma unroll
    for (int ni = 0; ni < 8; ni++)
        #pragma unroll
        for (int r = 0; r < 4; r++) acc[ni][r] = 0.f;

    const int rloc0 = w * 16 + g;
    const int row0  = q0 + rloc0;
    const int row1  = row0 + 8;

    const uint32_t* Qs = fsm;

    #pragma unroll 1
    for (int kt = 0; kt < nt; kt++) {
        if (kt + 1 < nt) { CPA_WAIT1(); } else { CPA_WAIT0(); }
        __syncthreads();
        if (kt + 2 < nt) { ISSUE_KV(kt + 2, (kt + 2) % 3); CPA_COMMIT(); }

        const uint32_t* Ks = fsm + SK_OFF + (kt % 3) * STG_SZ;
        const uint32_t* Vs = Ks + FK * HSTR;
        const int k0 = kt * FK;

        float sc[8][4];
        #pragma unroll
        for (int ni = 0; ni < 8; ni++)
            #pragma unroll
            for (int r = 0; r < 4; r++) sc[ni][r] = 0.f;

        #pragma unroll
        for (int kk = 0; kk < 4; kk++) {
            uint32_t a[4];
            const int r0b = rloc0 * HSTR + 8 * kk + tg;
            a[0] = Qs[r0b];
            a[1] = Qs[r0b + 8 * HSTR];
            a[2] = Qs[r0b + 4];
            a[3] = Qs[r0b + 8 * HSTR + 4];
            #pragma unroll
            for (int ni = 0; ni < 8; ni++) {
                uint32_t b[2];
                const int nb = (ni * 8 + g) * HSTR + 8 * kk + tg;
                b[0] = Ks[nb];
                b[1] = Ks[nb + 4];
                mma_fp16(sc[ni], a, b);
            }
        }

        if (kt >= 2 * qt) {
            #pragma unroll
            for (int ni = 0; ni < 8; ni++) {
                const int c = k0 + ni * 8 + 2 * tg;
                if (c     > row0) sc[ni][0] = -1e30f;
                if (c + 1 > row0) sc[ni][1] = -1e30f;
                if (c     > row1) sc[ni][2] = -1e30f;
                if (c + 1 > row1) sc[ni][3] = -1e30f;
            }
        }

        // base-2 online softmax (log2e folded into Q)
        float mx0 = -1e30f, mx1 = -1e30f;
        #pragma unroll
        for (int ni = 0; ni < 8; ni++) {
            mx0 = fmaxf(mx0, fmaxf(sc[ni][0], sc[ni][1]));
            mx1 = fmaxf(mx1, fmaxf(sc[ni][2], sc[ni][3]));
        }
        #pragma unroll
        for (int off = 1; off < 4; off <<= 1) {
            mx0 = fmaxf(mx0, __shfl_xor_sync(0xffffffffu, mx0, off));
            mx1 = fmaxf(mx1, __shfl_xor_sync(0xffffffffu, mx1, off));
        }
        const float mn0 = fmaxf(m0r, mx0);
        const float mn1 = fmaxf(m1r, mx1);
        const float al0 = exp2f(m0r - mn0);
        const float al1 = exp2f(m1r - mn1);

        float s0 = 0.f, s1 = 0.f;
        #pragma unroll
        for (int ni = 0; ni < 8; ni++) {
            sc[ni][0] = exp2f(sc[ni][0] - mn0);
            sc[ni][1] = exp2f(sc[ni][1] - mn0);
            sc[ni][2] = exp2f(sc[ni][2] - mn1);
            sc[ni][3] = exp2f(sc[ni][3] - mn1);
            s0 += sc[ni][0] + sc[ni][1];
            s1 += sc[ni][2] + sc[ni][3];
        }
        #pragma unroll
        for (int off = 1; off < 4; off <<= 1) {
            s0 += __shfl_xor_sync(0xffffffffu, s0, off);
            s1 += __shfl_xor_sync(0xffffffffu, s1, off);
        }
        l0 = l0 * al0 + s0;
        l1 = l1 * al1 + s1;
        m0r = mn0; m1r = mn1;

        uint32_t ph[8][2];
        #pragma unroll
        for (int ni = 0; ni < 8; ni++) {
            acc[ni][0] *= al0; acc[ni][1] *= al0;
            acc[ni][2] *= al1; acc[ni][3] *= al1;
            ph[ni][0] = fpack(sc[ni][0], sc[ni][1]);
            ph[ni][1] = fpack(sc[ni][2], sc[ni][3]);
        }

        #pragma unroll
        for (int kk = 0; kk < 4; kk++) {
            uint32_t a[4];
            a[0] = ph[2 * kk][0];
            a[1] = ph[2 * kk][1];
            a[2] = ph[2 * kk + 1][0];
            a[3] = ph[2 * kk + 1][1];
            #pragma unroll
            for (int ni = 0; ni < 8; ni++) {
                uint32_t b[2];
                const int nb = (ni * 8 + g) * HSTR + 8 * kk + tg;
                b[0] = Vs[nb];
                b[1] = Vs[nb + 4];
                mma_fp16(acc[ni], a, b);
            }
        }
    }

    const float il0 = 1.f / l0;
    const float il1 = 1.f / l1;
    const int b_ = bh >> 4, nh = bh & 15;
    #pragma unroll
    for (int ni = 0; ni < 8; ni++) {
        const int cp = nh * 32 + ni * 4 + tg;
        AOh[(size_t)(b_ * SS + row0) * HP + cp] =
            fpack(acc[ni][0] * il0, acc[ni][1] * il0);
        AOh[(size_t)(b_ * SS + row1) * HP + cp] =
            fpack(acc[ni][2] * il1, acc[ni][3] * il1);
    }
    #undef ISSUE_KV
}

// ---------------- launcher ---------------------------------------------------
extern "C" void kernel_launch(void* const* d_in, const int* in_sizes, int n_in,
                              void* d_out, int out_size)
{
    (void)in_sizes; (void)n_in; (void)out_size;
    const float* hs = (const float*)d_in[0];
    const float* wq = (const float*)d_in[2];
    const float* wk = (const float*)d_in[3];
    const float* wv = (const float*)d_in[4];
    const float* wo = (const float*)d_in[5];
    const int*  pos = (const int*)d_in[6];
    float* out = (float*)d_out;

    uint32_t *Hh, *Wqh, *Wkh, *Wvh, *Woh, *AOh, *Qh, *Kh, *Vt, *Vh;
    float2* tab;
    cudaGetSymbolAddress((void**)&Hh,  g_Hh);
    cudaGetSymbolAddress((void**)&Wqh, g_Wqh);
    cudaGetSymbolAddress((void**)&Wkh, g_Wkh);
    cudaGetSymbolAddress((void**)&Wvh, g_Wvh);
    cudaGetSymbolAddress((void**)&Woh, g_Woh);
    cudaGetSymbolAddress((void**)&AOh, g_AOh);
    cudaGetSymbolAddress((void**)&Qh,  g_Qh);
    cudaGetSymbolAddress((void**)&Kh,  g_Kh);
    cudaGetSymbolAddress((void**)&Vt,  g_Vt);
    cudaGetSymbolAddress((void**)&Vh,  g_Vh);
    cudaGetSymbolAddress((void**)&tab, g_tab);

    static bool attr_done = false;
    if (!attr_done) {
        cudaFuncSetAttribute(gemm_v7<0>,
                             cudaFuncAttributeMaxDynamicSharedMemorySize, GEMM_SMEM);
        cudaFuncSetAttribute(gemm_v7<1>,
                             cudaFuncAttributeMaxDynamicSharedMemorySize, GEMM_SMEM);
        cudaFuncSetAttribute(flash_fp16,
                             cudaFuncAttributeMaxDynamicSharedMemorySize, FLASH_SMEM);
        attr_done = true;
    }

    pack_all<<<1024, 256>>>(hs, wq, wk, wv, wo, Hh, Wqh, Wkh, Wvh, Woh, tab);

    gemm_v7<0><<<dim3(HH/GTN, MM/GTM, 3), 256, GEMM_SMEM>>>(
        Hh, Wqh, Wkh, Wvh, Qh, Kh, Vt, tab, pos);

    prep_v2<<<dim3(SS/64, BB*NHH), 256>>>(Vt, Vh);

    flash_fp16<<<dim3(SS/FQ, BB*NHH), 256, FLASH_SMEM>>>(Qh, Kh, Vh, AOh);

    gemm_v7<1><<<dim3(HH/GTN, MM/GTM, 1), 256, GEMM_SMEM>>>(
        AOh, Woh, Woh, Woh, out, out, out, tab, pos);
}

// round 13
// speedup vs baseline: 1.1501x; 1.0444x over previous
#include <cuda_runtime.h>
#include <cuda_fp16.h>
#include <cstdint>
#include <math.h>

#define BB 2
#define SS 2048
#define HH 1024
#define NHH 16
#define HDD 64
#define MM (BB*SS)   // 4096
#define HP (HH/2)    // 512 u32 per packed row

// ---------------- scratch (allocation-free: device globals) ----------------
__device__ uint32_t g_Hh [MM*HP];
__device__ uint32_t g_Wqh[HH*HP];
__device__ uint32_t g_Wkh[HH*HP];
__device__ uint32_t g_Wvh[HH*HP];
__device__ uint32_t g_Woh[HH*HP];
__device__ uint32_t g_AOh[MM*HP];
__device__ uint32_t g_Qh[BB*NHH*SS*(HDD/2)];
__device__ uint32_t g_Kh[BB*NHH*SS*(HDD/2)];
__device__ uint32_t g_Vt[BB*NHH*SS*(HDD/2)];
__device__ uint32_t g_Vh[BB*NHH*HDD*(SS/2)];
__device__ float2   g_tab[SS*32];

// ---------------- helpers ----------------------------------------------------
__device__ __forceinline__ uint32_t fpack(float a, float b) {
    __half2 h = __floats2half2_rn(a, b);
    return *reinterpret_cast<uint32_t*>(&h);
}

// layout map: within each 32-u32 block, logical col -> physical col
//   pair perm on bits 0..2:  (tg, tg+4) -> (2tg, 2tg+1)
//   XOR swizzle on bits 3..4 by (row & 3)
__device__ __forceinline__ int pcol(int c32, int key) {
    const int c = c32 & 7;
    return ((c32 & 24) ^ (key << 3)) | (((c & 3) << 1) | ((c >> 2) & 1));
}

__device__ __forceinline__ void mma_fp16(float c[4], const uint32_t a[4], const uint32_t b[2]) {
    asm volatile(
        "mma.sync.aligned.m16n8k16.row.col.f32.f16.f16.f32 "
        "{%0,%1,%2,%3}, {%4,%5,%6,%7}, {%8,%9}, {%0,%1,%2,%3};"
        : "+f"(c[0]), "+f"(c[1]), "+f"(c[2]), "+f"(c[3])
        : "r"(a[0]), "r"(a[1]), "r"(a[2]), "r"(a[3]),
          "r"(b[0]), "r"(b[1]));
}

__device__ __forceinline__ uint32_t smem_u32(const void* p) {
    uint32_t a;
    asm("{ .reg .u64 t; cvta.to.shared.u64 t, %1; cvt.u32.u64 %0, t; }" : "=r"(a) : "l"(p));
    return a;
}

#define CPA16(dst, src) \
    asm volatile("cp.async.cg.shared.global [%0], [%1], 16;" :: "r"(dst), "l"(src))
#define CPA_COMMIT() asm volatile("cp.async.commit_group;" ::: "memory")
#define CPA_WAIT0()  asm volatile("cp.async.wait_group 0;" ::: "memory")
#define CPA_WAIT1()  asm volatile("cp.async.wait_group 1;" ::: "memory")

#define LOG2E 1.4426950408889634f

// ---------------- fused pack + rope table (writes permuted layout) ----------
#define NHS (MM*HP)
#define NWW (HH*HP)
#define NTAB (SS*32)
__global__ void __launch_bounds__(256) pack_all(const float* __restrict__ hs,
                                                const float* __restrict__ wq,
                                                const float* __restrict__ wk,
                                                const float* __restrict__ wv,
                                                const float* __restrict__ wo,
                                                uint32_t* __restrict__ Hh,
                                                uint32_t* __restrict__ Wqh,
                                                uint32_t* __restrict__ Wkh,
                                                uint32_t* __restrict__ Wvh,
                                                uint32_t* __restrict__ Woh,
                                                float2* __restrict__ tab)
{
    const int total = NTAB + NHS + 4 * NWW;
    int i = blockIdx.x * blockDim.x + threadIdx.x;
    const int stride = gridDim.x * blockDim.x;
    for (; i < total; i += stride) {
        if (i < NTAB) {
            const int p = i >> 5, fi = i & 31;
            const float inv = expf(-(float)fi * (logf(10000.0f) / 32.0f));
            float sn, cs;
            sincosf((float)p * inv, &sn, &cs);
            tab[i] = make_float2(cs, sn);
            continue;
        }
        const int t = i - NTAB;
        const float* s; uint32_t* d; int idx;
        if (t < NHS) { s = hs; d = Hh; idx = t; }
        else {
            const int j = t - NHS;
            const int wsel = j >> 19;
            idx = j & (NWW - 1);
            switch (wsel) {
                case 0: s = wq; d = Wqh; break;
                case 1: s = wk; d = Wkh; break;
                case 2: s = wv; d = Wvh; break;
                default: s = wo; d = Woh; break;
            }
        }
        float2 v = ((const float2*)s)[idx];
        const int key = (idx >> 9) & 3;                         // row & 3
        const int out_idx = (idx & ~31) | pcol(idx & 31, key);  // permuted col
        d[out_idx] = fpack(v.x, v.y);
    }
}

// ---------------- GEMM v8: fp16, 128x128 CTA, K-chunk 64, LDS.64 fragments --
// Stage: 256 rows x 32 u32 (no padding; swizzle is baked in global layout).
#define GTM 128
#define GTN 128
#define GSTAGE ((GTM + GTN) * 32)       // 8192 u32
static const int GEMM_SMEM = 3 * GSTAGE * (int)sizeof(uint32_t);  // 98304

template<int MODE>
__global__ void __launch_bounds__(256, 2) gemm_v8(const uint32_t* __restrict__ A,
                                                  const uint32_t* __restrict__ B0,
                                                  const uint32_t* __restrict__ B1,
                                                  const uint32_t* __restrict__ B2,
                                                  void* __restrict__ Y0v,
                                                  void* __restrict__ Y1v,
                                                  void* __restrict__ Y2v,
                                                  const float2* __restrict__ tab,
                                                  const int* __restrict__ pos_ids)
{
    extern __shared__ uint32_t sm4[];
    const int z = blockIdx.z;
    const uint32_t* Bp = (z == 0) ? B0 : (z == 1) ? B1 : B2;
    void* Yv           = (z == 0) ? Y0v : (z == 1) ? Y1v : Y2v;

    const int tid  = threadIdx.x;
    const int w    = tid >> 5;
    const int lane = tid & 31;
    const int g    = lane >> 2;
    const int tg   = lane & 3;
    const int gk   = (g & 3) << 3;       // swizzle key bits
    const int wm   = (w & 3) * 32;
    const int wn   = (w >> 2) * 64;
    const int m0   = blockIdx.y * GTM;
    const int n0   = blockIdx.x * GTN;
    const uint32_t sb = smem_u32(sm4);

    // 2048 16B-chunks per stage (256 rows x 8); 8 per thread; verbatim copy
    #define ISSUE_G(IT, STG)                                                      \
        _Pragma("unroll")                                                         \
        for (int i = 0; i < 8; i++) {                                             \
            const int c = tid + i * 256;                                          \
            const int row = c >> 3, j = c & 7;                                    \
            const uint32_t* src = (row < GTM)                                     \
                ? A  + (size_t)(m0 + row)       * HP + (IT) * 32 + j * 4          \
                : Bp + (size_t)(n0 + row - GTM) * HP + (IT) * 32 + j * 4;         \
            CPA16(sb + ((STG) * GSTAGE + row * 32 + j * 4) * 4, src);             \
        }

    ISSUE_G(0, 0); CPA_COMMIT();
    ISSUE_G(1, 1); CPA_COMMIT();

    float acc[2][8][4];
    #pragma unroll
    for (int mi = 0; mi < 2; mi++)
        #pragma unroll
        for (int ni = 0; ni < 8; ni++)
            #pragma unroll
            for (int r = 0; r < 4; r++) acc[mi][ni][r] = 0.f;

    const int NIT = HP / 32;             // 16
    #pragma unroll 1
    for (int it = 0; it < NIT; it++) {
        if (it < NIT - 1) { CPA_WAIT1(); } else { CPA_WAIT0(); }
        __syncthreads();
        if (it + 2 < NIT) {
            ISSUE_G(it + 2, (it + 2) % 3);
            CPA_COMMIT();
        }

        const uint32_t* cS = sm4 + (it % 3) * GSTAGE;
        const uint32_t* cB = cS + GTM * 32;

        #pragma unroll
        for (int kk = 0; kk < 4; kk++) {
            const int off = ((kk * 8 + 2 * tg) ^ gk);
            uint32_t a[2][4], b[8][2];
            #pragma unroll
            for (int mi = 0; mi < 2; mi++) {
                const int r0 = (wm + 16 * mi + g) * 32 + off;
                uint2 p0 = *(const uint2*)&cS[r0];
                uint2 p1 = *(const uint2*)&cS[r0 + 8 * 32];
                a[mi][0] = p0.x; a[mi][2] = p0.y;
                a[mi][1] = p1.x; a[mi][3] = p1.y;
            }
            #pragma unroll
            for (int ni = 0; ni < 8; ni++) {
                uint2 pb = *(const uint2*)&cB[(wn + 8 * ni + g) * 32 + off];
                b[ni][0] = pb.x; b[ni][1] = pb.y;
            }
            #pragma unroll
            for (int mi = 0; mi < 2; mi++)
                #pragma unroll
                for (int ni = 0; ni < 8; ni++)
                    mma_fp16(acc[mi][ni], a[mi], b[ni]);
        }
    }

    if (MODE == 0) {
        uint32_t* Yh = (uint32_t*)Yv;
        const int nh = (n0 + wn) >> 6;
        const float qsc = (z == 0) ? (0.125f * LOG2E) : 1.0f;
        #pragma unroll
        for (int mi = 0; mi < 2; mi++) {
            #pragma unroll
            for (int half = 0; half < 2; half++) {
                const int row = m0 + wm + 16 * mi + g + 8 * half;
                const int k0  = 2 * half;
                const int b_  = row >> 11;
                const int s   = row & (SS - 1);
                const int key = row & 3;
                const size_t ob = ((size_t)(b_ * NHH + nh) * SS + s) * 32;
                if (z < 2) {
                    int p = pos_ids[b_ * SS + s];
                    p = min(max(p, 0), SS - 1);
                    const float2* tb = tab + p * 32;
                    #pragma unroll
                    for (int ni = 0; ni < 4; ni++) {
                        const int i0 = 8 * ni + 2 * tg;
                        const float2 t0 = tb[i0];
                        const float2 t1 = tb[i0 + 1];
                        const float lo0 = acc[mi][ni][k0],     lo1 = acc[mi][ni][k0 + 1];
                        const float hi0 = acc[mi][ni + 4][k0], hi1 = acc[mi][ni + 4][k0 + 1];
                        const float nl0 = (lo0 * t0.x - hi0 * t0.y) * qsc;
                        const float nl1 = (lo1 * t1.x - hi1 * t1.y) * qsc;
                        const float nh0 = (hi0 * t0.x + lo0 * t0.y) * qsc;
                        const float nh1 = (hi1 * t1.x + lo1 * t1.y) * qsc;
                        const int c1 = 4 * ni + tg;          // logical d-pair 0..15
                        const int c2 = 16 + 4 * ni + tg;     // logical d-pair 16..31
                        Yh[ob + pcol(c1, key)] = fpack(nl0, nl1);
                        Yh[ob + pcol(c2, key)] = fpack(nh0, nh1);
                    }
                } else {
                    // V: logical layout (consumed by prep_v2, unpermuted)
                    #pragma unroll
                    for (int ni = 0; ni < 8; ni++)
                        Yh[ob + 4 * ni + tg] = fpack(acc[mi][ni][k0], acc[mi][ni][k0 + 1]);
                }
            }
        }
    } else {
        float* Y = (float*)Yv;
        #pragma unroll
        for (int mi = 0; mi < 2; mi++) {
            #pragma unroll
            for (int ni = 0; ni < 8; ni++) {
                const int row = m0 + wm + 16 * mi + g;
                const int col = n0 + wn + 8 * ni + 2 * tg;
                *(float2*)&Y[(size_t)row * HH + col] =
                    make_float2(acc[mi][ni][0], acc[mi][ni][1]);
                *(float2*)&Y[(size_t)(row + 8) * HH + col] =
                    make_float2(acc[mi][ni][2], acc[mi][ni][3]);
            }
        }
    }
    #undef ISSUE_G
}

// ---------------- prep_v2: fp16 [bh][s][dp] -> fp16 [bh][d][sp] (logical) ---
__global__ void __launch_bounds__(256) prep_v2(const uint32_t* __restrict__ Vt,
                                               uint32_t* __restrict__ Vh)
{
    __shared__ uint32_t vs[64 * 36];
    const int tid = threadIdx.x;
    const int bh  = blockIdx.y;
    const int st  = blockIdx.x * 64;
    const uint32_t* src = Vt + ((size_t)bh * SS + st) * 32;

    #pragma unroll
    for (int i = 0; i < 2; i++) {
        const int c = tid + i * 256;
        const int row = c >> 3, j = c & 7;
        uint4 v = *(const uint4*)&src[(size_t)row * 32 + j * 4];
        *(uint4*)&vs[row * 36 + j * 4] = v;
    }
    __syncthreads();

    const int d  = tid & 63;
    const int dp = d >> 1;
    const int sh = (d & 1) * 16;
    #pragma unroll
    for (int i = 0; i < 2; i++) {
        const int q = (tid >> 6) + i * 4;
        uint32_t o[4];
        #pragma unroll
        for (int k = 0; k < 4; k++) {
            const int sp = 4 * q + k;
            const uint32_t w0 = vs[(2 * sp) * 36 + dp];
            const uint32_t w1 = vs[(2 * sp + 1) * 36 + dp];
            o[k] = ((w0 >> sh) & 0xffffu) | (((w1 >> sh) & 0xffffu) << 16);
        }
        *(uint4*)&Vh[((size_t)bh * HDD + d) * (SS / 2) + (st >> 1) + 4 * q] =
            make_uint4(o[0], o[1], o[2], o[3]);
    }
}

// ---------------- flash attention: fp16 MMA, LDS.64 Q/K fragments -----------
#define FQ 128
#define FK 64
#define VSTR 36
#define SQ_OFF 0
#define SK_OFF (FQ * 32)                 // 4096
#define SV_OFF (FK * 32)                 // V region offset within stage: 2048
#define STG_SZ (FK * 32 + FK * VSTR)     // 4352 u32
static const int FLASH_SMEM = (FQ * 32 + 3 * STG_SZ) * (int)sizeof(uint32_t);  // 68608

__global__ void __launch_bounds__(256, 2) flash_fp16(const uint32_t* __restrict__ Qh,
                                                     const uint32_t* __restrict__ Kh,
                                                     const uint32_t* __restrict__ Vh,
                                                     uint32_t* __restrict__ AOh)
{
    extern __shared__ uint32_t fsm[];
    const uint32_t sb = smem_u32(fsm);

    const int tid  = threadIdx.x;
    const int w    = tid >> 5;
    const int lane = tid & 31;
    const int g    = lane >> 2;
    const int tg   = lane & 3;
    const int gk   = (g & 3) << 3;
    const int bh   = blockIdx.y;
    const int qt   = (int)(gridDim.x - 1) - (int)blockIdx.x;
    const int q0   = qt * FQ;

    const uint32_t* qsrc = Qh + ((size_t)bh * SS + q0) * 32;
    const uint32_t* ksrc = Kh + (size_t)bh * SS * 32;
    const uint32_t* vsrc = Vh + (size_t)bh * HDD * (SS / 2);

    const int nt = 2 * qt + 2;

    #define ISSUE_KV(KT, STG)                                                     \
        {                                                                         \
            _Pragma("unroll")                                                     \
            for (int i = 0; i < 2; i++) {                                         \
                const int c = tid + i * 256;                                      \
                const int row = c >> 3, j = c & 7;                                \
                CPA16(sb + (SK_OFF + (STG) * STG_SZ + row * 32 + j * 4) * 4,      \
                      ksrc + ((size_t)(KT) * FK + row) * 32 + j * 4);             \
            }                                                                     \
            _Pragma("unroll")                                                     \
            for (int i = 0; i < 2; i++) {                                         \
                const int c = tid + i * 256;                                      \
                const int d = c >> 3, j = c & 7;                                  \
                CPA16(sb + (SK_OFF + (STG) * STG_SZ + SV_OFF + d * VSTR + j * 4) * 4, \
                      vsrc + (size_t)d * (SS / 2) + (KT) * 32 + j * 4);           \
            }                                                                     \
        }

    #pragma unroll
    for (int i = 0; i < 4; i++) {
        const int c = tid + i * 256;
        const int row = c >> 3, j = c & 7;
        CPA16(sb + (SQ_OFF + row * 32 + j * 4) * 4, qsrc + (size_t)row * 32 + j * 4);
    }
    ISSUE_KV(0, 0);
    CPA_COMMIT();
    if (nt > 1) { ISSUE_KV(1, 1); CPA_COMMIT(); }

    float m0r = -1e30f, m1r = -1e30f, l0 = 0.f, l1 = 0.f;
    float acc[8][4];
    #pragma unroll
    for (int ni = 0; ni < 8; ni++)
        #pragma unroll
        for (int r = 0; r < 4; r++) acc[ni][r] = 0.f;

    const int rloc0 = w * 16 + g;
    const int row0  = q0 + rloc0;
    const int row1  = row0 + 8;

    const uint32_t* Qs = fsm;

    #pragma unroll 1
    for (int kt = 0; kt < nt; kt++) {
        if (kt + 1 < nt) { CPA_WAIT1(); } else { CPA_WAIT0(); }
        __syncthreads();
        if (kt + 2 < nt) { ISSUE_KV(kt + 2, (kt + 2) % 3); CPA_COMMIT(); }

        const uint32_t* Ks = fsm + SK_OFF + (kt % 3) * STG_SZ;
        const uint32_t* Vs = Ks + SV_OFF;
        const int k0 = kt * FK;

        float sc[8][4];
        #pragma unroll
        for (int ni = 0; ni < 8; ni++)
            #pragma unroll
            for (int r = 0; r < 4; r++) sc[ni][r] = 0.f;

        #pragma unroll
        for (int kk = 0; kk < 4; kk++) {
            const int off = ((kk * 8 + 2 * tg) ^ gk);
            uint32_t a[4];
            {
                uint2 p0 = *(const uint2*)&Qs[rloc0 * 32 + off];
                uint2 p1 = *(const uint2*)&Qs[(rloc0 + 8) * 32 + off];
                a[0] = p0.x; a[2] = p0.y;
                a[1] = p1.x; a[3] = p1.y;
            }
            #pragma unroll
            for (int ni = 0; ni < 8; ni++) {
                uint2 pb = *(const uint2*)&Ks[(ni * 8 + g) * 32 + off];
                uint32_t b[2] = {pb.x, pb.y};
                mma_fp16(sc[ni], a, b);
            }
        }

        if (kt >= 2 * qt) {
            #pragma unroll
            for (int ni = 0; ni < 8; ni++) {
                const int c = k0 + ni * 8 + 2 * tg;
                if (c     > row0) sc[ni][0] = -1e30f;
                if (c + 1 > row0) sc[ni][1] = -1e30f;
                if (c     > row1) sc[ni][2] = -1e30f;
                if (c + 1 > row1) sc[ni][3] = -1e30f;
            }
        }

        float mx0 = -1e30f, mx1 = -1e30f;
        #pragma unroll
        for (int ni = 0; ni < 8; ni++) {
            mx0 = fmaxf(mx0, fmaxf(sc[ni][0], sc[ni][1]));
            mx1 = fmaxf(mx1, fmaxf(sc[ni][2], sc[ni][3]));
        }
        #pragma unroll
        for (int off = 1; off < 4; off <<= 1) {
            mx0 = fmaxf(mx0, __shfl_xor_sync(0xffffffffu, mx0, off));
            mx1 = fmaxf(mx1, __shfl_xor_sync(0xffffffffu, mx1, off));
        }
        const float mn0 = fmaxf(m0r, mx0);
        const float mn1 = fmaxf(m1r, mx1);
        const float al0 = exp2f(m0r - mn0);
        const float al1 = exp2f(m1r - mn1);

        float s0 = 0.f, s1 = 0.f;
        #pragma unroll
        for (int ni = 0; ni < 8; ni++) {
            sc[ni][0] = exp2f(sc[ni][0] - mn0);
            sc[ni][1] = exp2f(sc[ni][1] - mn0);
            sc[ni][2] = exp2f(sc[ni][2] - mn1);
            sc[ni][3] = exp2f(sc[ni][3] - mn1);
            s0 += sc[ni][0] + sc[ni][1];
            s1 += sc[ni][2] + sc[ni][3];
        }
        #pragma unroll
        for (int off = 1; off < 4; off <<= 1) {
            s0 += __shfl_xor_sync(0xffffffffu, s0, off);
            s1 += __shfl_xor_sync(0xffffffffu, s1, off);
        }
        l0 = l0 * al0 + s0;
        l1 = l1 * al1 + s1;
        m0r = mn0; m1r = mn1;

        uint32_t ph[8][2];
        #pragma unroll
        for (int ni = 0; ni < 8; ni++) {
            acc[ni][0] *= al0; acc[ni][1] *= al0;
            acc[ni][2] *= al1; acc[ni][3] *= al1;
            ph[ni][0] = fpack(sc[ni][0], sc[ni][1]);
            ph[ni][1] = fpack(sc[ni][2], sc[ni][3]);
        }

        #pragma unroll
        for (int kk = 0; kk < 4; kk++) {
            const int kc = kk * 8;
            uint32_t a[4];
            a[0] = ph[2 * kk][0];
            a[1] = ph[2 * kk][1];
            a[2] = ph[2 * kk + 1][0];
            a[3] = ph[2 * kk + 1][1];
            #pragma unroll
            for (int ni = 0; ni < 8; ni++) {
                uint32_t b[2];
                // V smem is [d][s-pair]: row = d = 8ni+g, col = s-pair = kc+tg
                const int nb = (ni * 8 + g) * VSTR + kc + tg;
                b[0] = Vs[nb];
                b[1] = Vs[nb + 4];
                mma_fp16(acc[ni], a, b);
            }
        }
    }

    // epilogue: packed fp16 AO with permuted layout (consumed by gemm<1> A)
    const float il0 = 1.f / l0;
    const float il1 = 1.f / l1;
    const int b_ = bh >> 4, nh = bh & 15;
    const int key = row0 & 3;            // == row1 & 3
    #pragma unroll
    for (int ni = 0; ni < 8; ni++) {
        const int c32 = ni * 4 + tg;
        const int cp = nh * 32 + pcol(c32, key);
        AOh[(size_t)(b_ * SS + row0) * HP + cp] =
            fpack(acc[ni][0] * il0, acc[ni][1] * il0);
        AOh[(size_t)(b_ * SS + row1) * HP + cp] =
            fpack(acc[ni][2] * il1, acc[ni][3] * il1);
    }
    #undef ISSUE_KV
}

// ---------------- launcher ---------------------------------------------------
extern "C" void kernel_launch(void* const* d_in, const int* in_sizes, int n_in,
                              void* d_out, int out_size)
{
    (void)in_sizes; (void)n_in; (void)out_size;
    const float* hs = (const float*)d_in[0];
    const float* wq = (const float*)d_in[2];
    const float* wk = (const float*)d_in[3];
    const float* wv = (const float*)d_in[4];
    const float* wo = (const float*)d_in[5];
    const int*  pos = (const int*)d_in[6];
    float* out = (float*)d_out;

    uint32_t *Hh, *Wqh, *Wkh, *Wvh, *Woh, *AOh, *Qh, *Kh, *Vt, *Vh;
    float2* tab;
    cudaGetSymbolAddress((void**)&Hh,  g_Hh);
    cudaGetSymbolAddress((void**)&Wqh, g_Wqh);
    cudaGetSymbolAddress((void**)&Wkh, g_Wkh);
    cudaGetSymbolAddress((void**)&Wvh, g_Wvh);
    cudaGetSymbolAddress((void**)&Woh, g_Woh);
    cudaGetSymbolAddress((void**)&AOh, g_AOh);
    cudaGetSymbolAddress((void**)&Qh,  g_Qh);
    cudaGetSymbolAddress((void**)&Kh,  g_Kh);
    cudaGetSymbolAddress((void**)&Vt,  g_Vt);
    cudaGetSymbolAddress((void**)&Vh,  g_Vh);
    cudaGetSymbolAddress((void**)&tab, g_tab);

    static bool attr_done = false;
    if (!attr_done) {
        cudaFuncSetAttribute(gemm_v8<0>,
                             cudaFuncAttributeMaxDynamicSharedMemorySize, GEMM_SMEM);
        cudaFuncSetAttribute(gemm_v8<1>,
                             cudaFuncAttributeMaxDynamicSharedMemorySize, GEMM_SMEM);
        cudaFuncSetAttribute(flash_fp16,
                             cudaFuncAttributeMaxDynamicSharedMemorySize, FLASH_SMEM);
        attr_done = true;
    }

    pack_all<<<1024, 256>>>(hs, wq, wk, wv, wo, Hh, Wqh, Wkh, Wvh, Woh, tab);

    gemm_v8<0><<<dim3(HH/GTN, MM/GTM, 3), 256, GEMM_SMEM>>>(
        Hh, Wqh, Wkh, Wvh, Qh, Kh, Vt, tab, pos);

    prep_v2<<<dim3(SS/64, BB*NHH), 256>>>(Vt, Vh);

    flash_fp16<<<dim3(SS/FQ, BB*NHH), 256, FLASH_SMEM>>>(Qh, Kh, Vh, AOh);

    gemm_v8<1><<<dim3(HH/GTN, MM/GTM, 1), 256, GEMM_SMEM>>>(
        AOh, Woh, Woh, Woh, out, out, out, tab, pos);
}

// round 14
// speedup vs baseline: 1.1610x; 1.0095x over previous
#include <cuda_runtime.h>
#include <cuda_fp16.h>
#include <cstdint>
#include <math.h>

#define BB 2
#define SS 2048
#define HH 1024
#define NHH 16
#define HDD 64
#define MM (BB*SS)   // 4096
#define HP (HH/2)    // 512 u32 per packed row

// ---------------- scratch (allocation-free: device globals) ----------------
__device__ uint32_t g_Hh [MM*HP];
__device__ uint32_t g_Wqh[HH*HP];
__device__ uint32_t g_Wkh[HH*HP];
__device__ uint32_t g_Wvh[HH*HP];
__device__ uint32_t g_Woh[HH*HP];
__device__ uint32_t g_AOh[MM*HP];
__device__ uint32_t g_Qh[BB*NHH*SS*(HDD/2)];
__device__ uint32_t g_Kh[BB*NHH*SS*(HDD/2)];
__device__ uint32_t g_Vt[BB*NHH*SS*(HDD/2)];
__device__ uint32_t g_Vh[BB*NHH*HDD*(SS/2)];
__device__ float2   g_tab[SS*32];

// ---------------- helpers ----------------------------------------------------
__device__ __forceinline__ uint32_t fpack(float a, float b) {
    __half2 h = __floats2half2_rn(a, b);
    return *reinterpret_cast<uint32_t*>(&h);
}

// layout map: within each 32-u32 block, logical col -> physical col
//   pair perm on bits 0..2:  (tg, tg+4) -> (2tg, 2tg+1)
//   XOR swizzle on bits 3..4 by (row & 3)
__device__ __forceinline__ int pcol(int c32, int key) {
    const int c = c32 & 7;
    return ((c32 & 24) ^ (key << 3)) | (((c & 3) << 1) | ((c >> 2) & 1));
}

__device__ __forceinline__ void mma_fp16(float c[4], const uint32_t a[4], const uint32_t b[2]) {
    asm volatile(
        "mma.sync.aligned.m16n8k16.row.col.f32.f16.f16.f32 "
        "{%0,%1,%2,%3}, {%4,%5,%6,%7}, {%8,%9}, {%0,%1,%2,%3};"
        : "+f"(c[0]), "+f"(c[1]), "+f"(c[2]), "+f"(c[3])
        : "r"(a[0]), "r"(a[1]), "r"(a[2]), "r"(a[3]),
          "r"(b[0]), "r"(b[1]));
}

__device__ __forceinline__ uint32_t smem_u32(const void* p) {
    uint32_t a;
    asm("{ .reg .u64 t; cvta.to.shared.u64 t, %1; cvt.u32.u64 %0, t; }" : "=r"(a) : "l"(p));
    return a;
}

#define CPA16(dst, src) \
    asm volatile("cp.async.cg.shared.global [%0], [%1], 16;" :: "r"(dst), "l"(src))
#define CPA_COMMIT() asm volatile("cp.async.commit_group;" ::: "memory")
#define CPA_WAIT0()  asm volatile("cp.async.wait_group 0;" ::: "memory")
#define CPA_WAIT1()  asm volatile("cp.async.wait_group 1;" ::: "memory")

#define LOG2E 1.4426950408889634f

// ---------------- fused pack + rope table (writes permuted layout) ----------
#define NHS (MM*HP)
#define NWW (HH*HP)
#define NTAB (SS*32)
__global__ void __launch_bounds__(256) pack_all(const float* __restrict__ hs,
                                                const float* __restrict__ wq,
                                                const float* __restrict__ wk,
                                                const float* __restrict__ wv,
                                                const float* __restrict__ wo,
                                                uint32_t* __restrict__ Hh,
                                                uint32_t* __restrict__ Wqh,
                                                uint32_t* __restrict__ Wkh,
                                                uint32_t* __restrict__ Wvh,
                                                uint32_t* __restrict__ Woh,
                                                float2* __restrict__ tab)
{
    const int total = NTAB + NHS + 4 * NWW;
    int i = blockIdx.x * blockDim.x + threadIdx.x;
    const int stride = gridDim.x * blockDim.x;
    for (; i < total; i += stride) {
        if (i < NTAB) {
            const int p = i >> 5, fi = i & 31;
            const float inv = expf(-(float)fi * (logf(10000.0f) / 32.0f));
            float sn, cs;
            sincosf((float)p * inv, &sn, &cs);
            tab[i] = make_float2(cs, sn);
            continue;
        }
        const int t = i - NTAB;
        const float* s; uint32_t* d; int idx;
        if (t < NHS) { s = hs; d = Hh; idx = t; }
        else {
            const int j = t - NHS;
            const int wsel = j >> 19;
            idx = j & (NWW - 1);
            switch (wsel) {
                case 0: s = wq; d = Wqh; break;
                case 1: s = wk; d = Wkh; break;
                case 2: s = wv; d = Wvh; break;
                default: s = wo; d = Woh; break;
            }
        }
        float2 v = ((const float2*)s)[idx];
        const int key = (idx >> 9) & 3;                         // row & 3
        const int out_idx = (idx & ~31) | pcol(idx & 31, key);  // permuted col
        d[out_idx] = fpack(v.x, v.y);
    }
}

// ---------------- GEMM v8: fp16, 128x128 CTA, K-chunk 64, LDS.64 fragments --
#define GTM 128
#define GTN 128
#define GSTAGE ((GTM + GTN) * 32)       // 8192 u32
static const int GEMM_SMEM = 3 * GSTAGE * (int)sizeof(uint32_t);  // 98304

template<int MODE>
__global__ void __launch_bounds__(256, 2) gemm_v8(const uint32_t* __restrict__ A,
                                                  const uint32_t* __restrict__ B0,
                                                  const uint32_t* __restrict__ B1,
                                                  const uint32_t* __restrict__ B2,
                                                  void* __restrict__ Y0v,
                                                  void* __restrict__ Y1v,
                                                  void* __restrict__ Y2v,
                                                  const float2* __restrict__ tab,
                                                  const int* __restrict__ pos_ids)
{
    extern __shared__ uint32_t sm4[];
    const int z = blockIdx.z;
    const uint32_t* Bp = (z == 0) ? B0 : (z == 1) ? B1 : B2;
    void* Yv           = (z == 0) ? Y0v : (z == 1) ? Y1v : Y2v;

    const int tid  = threadIdx.x;
    const int w    = tid >> 5;
    const int lane = tid & 31;
    const int g    = lane >> 2;
    const int tg   = lane & 3;
    const int gk   = (g & 3) << 3;
    const int wm   = (w & 3) * 32;
    const int wn   = (w >> 2) * 64;
    const int m0   = blockIdx.y * GTM;
    const int n0   = blockIdx.x * GTN;
    const uint32_t sb = smem_u32(sm4);

    #define ISSUE_G(IT, STG)                                                      \
        _Pragma("unroll")                                                         \
        for (int i = 0; i < 8; i++) {                                             \
            const int c = tid + i * 256;                                          \
            const int row = c >> 3, j = c & 7;                                    \
            const uint32_t* src = (row < GTM)                                     \
                ? A  + (size_t)(m0 + row)       * HP + (IT) * 32 + j * 4          \
                : Bp + (size_t)(n0 + row - GTM) * HP + (IT) * 32 + j * 4;         \
            CPA16(sb + ((STG) * GSTAGE + row * 32 + j * 4) * 4, src);             \
        }

    ISSUE_G(0, 0); CPA_COMMIT();
    ISSUE_G(1, 1); CPA_COMMIT();

    float acc[2][8][4];
    #pragma unroll
    for (int mi = 0; mi < 2; mi++)
        #pragma unroll
        for (int ni = 0; ni < 8; ni++)
            #pragma unroll
            for (int r = 0; r < 4; r++) acc[mi][ni][r] = 0.f;

    const int NIT = HP / 32;             // 16
    #pragma unroll 1
    for (int it = 0; it < NIT; it++) {
        if (it < NIT - 1) { CPA_WAIT1(); } else { CPA_WAIT0(); }
        __syncthreads();
        if (it + 2 < NIT) {
            ISSUE_G(it + 2, (it + 2) % 3);
            CPA_COMMIT();
        }

        const uint32_t* cS = sm4 + (it % 3) * GSTAGE;
        const uint32_t* cB = cS + GTM * 32;

        #pragma unroll
        for (int kk = 0; kk < 4; kk++) {
            const int off = ((kk * 8 + 2 * tg) ^ gk);
            uint32_t a[2][4], b[8][2];
            #pragma unroll
            for (int mi = 0; mi < 2; mi++) {
                const int r0 = (wm + 16 * mi + g) * 32 + off;
                uint2 p0 = *(const uint2*)&cS[r0];
                uint2 p1 = *(const uint2*)&cS[r0 + 8 * 32];
                a[mi][0] = p0.x; a[mi][2] = p0.y;
                a[mi][1] = p1.x; a[mi][3] = p1.y;
            }
            #pragma unroll
            for (int ni = 0; ni < 8; ni++) {
                uint2 pb = *(const uint2*)&cB[(wn + 8 * ni + g) * 32 + off];
                b[ni][0] = pb.x; b[ni][1] = pb.y;
            }
            #pragma unroll
            for (int mi = 0; mi < 2; mi++)
                #pragma unroll
                for (int ni = 0; ni < 8; ni++)
                    mma_fp16(acc[mi][ni], a[mi], b[ni]);
        }
    }

    if (MODE == 0) {
        uint32_t* Yh = (uint32_t*)Yv;
        const int nh = (n0 + wn) >> 6;
        const float qsc = (z == 0) ? (0.125f * LOG2E) : 1.0f;
        #pragma unroll
        for (int mi = 0; mi < 2; mi++) {
            #pragma unroll
            for (int half = 0; half < 2; half++) {
                const int row = m0 + wm + 16 * mi + g + 8 * half;
                const int k0  = 2 * half;
                const int b_  = row >> 11;
                const int s   = row & (SS - 1);
                const int key = row & 3;
                const size_t ob = ((size_t)(b_ * NHH + nh) * SS + s) * 32;
                if (z < 2) {
                    int p = pos_ids[b_ * SS + s];
                    p = min(max(p, 0), SS - 1);
                    const float2* tb = tab + p * 32;
                    #pragma unroll
                    for (int ni = 0; ni < 4; ni++) {
                        const int i0 = 8 * ni + 2 * tg;
                        const float2 t0 = tb[i0];
                        const float2 t1 = tb[i0 + 1];
                        const float lo0 = acc[mi][ni][k0],     lo1 = acc[mi][ni][k0 + 1];
                        const float hi0 = acc[mi][ni + 4][k0], hi1 = acc[mi][ni + 4][k0 + 1];
                        const float nl0 = (lo0 * t0.x - hi0 * t0.y) * qsc;
                        const float nl1 = (lo1 * t1.x - hi1 * t1.y) * qsc;
                        const float nh0 = (hi0 * t0.x + lo0 * t0.y) * qsc;
                        const float nh1 = (hi1 * t1.x + lo1 * t1.y) * qsc;
                        const int c1 = 4 * ni + tg;
                        const int c2 = 16 + 4 * ni + tg;
                        Yh[ob + pcol(c1, key)] = fpack(nl0, nl1);
                        Yh[ob + pcol(c2, key)] = fpack(nh0, nh1);
                    }
                } else {
                    #pragma unroll
                    for (int ni = 0; ni < 8; ni++)
                        Yh[ob + 4 * ni + tg] = fpack(acc[mi][ni][k0], acc[mi][ni][k0 + 1]);
                }
            }
        }
    } else {
        float* Y = (float*)Yv;
        #pragma unroll
        for (int mi = 0; mi < 2; mi++) {
            #pragma unroll
            for (int ni = 0; ni < 8; ni++) {
                const int row = m0 + wm + 16 * mi + g;
                const int col = n0 + wn + 8 * ni + 2 * tg;
                *(float2*)&Y[(size_t)row * HH + col] =
                    make_float2(acc[mi][ni][0], acc[mi][ni][1]);
                *(float2*)&Y[(size_t)(row + 8) * HH + col] =
                    make_float2(acc[mi][ni][2], acc[mi][ni][3]);
            }
        }
    }
    #undef ISSUE_G
}

// ---------------- prep_v2: fp16 [bh][s][dp] -> fp16 [bh][d][sp] (logical) ---
__global__ void __launch_bounds__(256) prep_v2(const uint32_t* __restrict__ Vt,
                                               uint32_t* __restrict__ Vh)
{
    __shared__ uint32_t vs[64 * 36];
    const int tid = threadIdx.x;
    const int bh  = blockIdx.y;
    const int st  = blockIdx.x * 64;
    const uint32_t* src = Vt + ((size_t)bh * SS + st) * 32;

    #pragma unroll
    for (int i = 0; i < 2; i++) {
        const int c = tid + i * 256;
        const int row = c >> 3, j = c & 7;
        uint4 v = *(const uint4*)&src[(size_t)row * 32 + j * 4];
        *(uint4*)&vs[row * 36 + j * 4] = v;
    }
    __syncthreads();

    const int d  = tid & 63;
    const int dp = d >> 1;
    const int sh = (d & 1) * 16;
    #pragma unroll
    for (int i = 0; i < 2; i++) {
        const int q = (tid >> 6) + i * 4;
        uint32_t o[4];
        #pragma unroll
        for (int k = 0; k < 4; k++) {
            const int sp = 4 * q + k;
            const uint32_t w0 = vs[(2 * sp) * 36 + dp];
            const uint32_t w1 = vs[(2 * sp + 1) * 36 + dp];
            o[k] = ((w0 >> sh) & 0xffffu) | (((w1 >> sh) & 0xffffu) << 16);
        }
        *(uint4*)&Vh[((size_t)bh * HDD + d) * (SS / 2) + (st >> 1) + 4 * q] =
            make_uint4(o[0], o[1], o[2], o[3]);
    }
}

// ---------------- flash attention: fp16 MMA, interleaved exp2/GEMM2 ---------
#define FQ 128
#define FK 64
#define VSTR 36
#define SQ_OFF 0
#define SK_OFF (FQ * 32)                 // 4096
#define SV_OFF (FK * 32)                 // 2048
#define STG_SZ (FK * 32 + FK * VSTR)     // 4352 u32
static const int FLASH_SMEM = (FQ * 32 + 3 * STG_SZ) * (int)sizeof(uint32_t);  // 68608

__global__ void __launch_bounds__(256, 2) flash_fp16(const uint32_t* __restrict__ Qh,
                                                     const uint32_t* __restrict__ Kh,
                                                     const uint32_t* __restrict__ Vh,
                                                     uint32_t* __restrict__ AOh)
{
    extern __shared__ uint32_t fsm[];
    const uint32_t sb = smem_u32(fsm);

    const int tid  = threadIdx.x;
    const int w    = tid >> 5;
    const int lane = tid & 31;
    const int g    = lane >> 2;
    const int tg   = lane & 3;
    const int gk   = (g & 3) << 3;
    const int bh   = blockIdx.y;
    const int qt   = (int)(gridDim.x - 1) - (int)blockIdx.x;
    const int q0   = qt * FQ;

    const uint32_t* qsrc = Qh + ((size_t)bh * SS + q0) * 32;
    const uint32_t* ksrc = Kh + (size_t)bh * SS * 32;
    const uint32_t* vsrc = Vh + (size_t)bh * HDD * (SS / 2);

    const int nt = 2 * qt + 2;

    #define ISSUE_KV(KT, STG)                                                     \
        {                                                                         \
            _Pragma("unroll")                                                     \
            for (int i = 0; i < 2; i++) {                                         \
                const int c = tid + i * 256;                                      \
                const int row = c >> 3, j = c & 7;                                \
                CPA16(sb + (SK_OFF + (STG) * STG_SZ + row * 32 + j * 4) * 4,      \
                      ksrc + ((size_t)(KT) * FK + row) * 32 + j * 4);             \
            }                                                                     \
            _Pragma("unroll")                                                     \
            for (int i = 0; i < 2; i++) {                                         \
                const int c = tid + i * 256;                                      \
                const int d = c >> 3, j = c & 7;                                  \
                CPA16(sb + (SK_OFF + (STG) * STG_SZ + SV_OFF + d * VSTR + j * 4) * 4, \
                      vsrc + (size_t)d * (SS / 2) + (KT) * 32 + j * 4);           \
            }                                                                     \
        }

    #pragma unroll
    for (int i = 0; i < 4; i++) {
        const int c = tid + i * 256;
        const int row = c >> 3, j = c & 7;
        CPA16(sb + (SQ_OFF + row * 32 + j * 4) * 4, qsrc + (size_t)row * 32 + j * 4);
    }
    ISSUE_KV(0, 0);
    CPA_COMMIT();
    if (nt > 1) { ISSUE_KV(1, 1); CPA_COMMIT(); }

    float m0r = -1e30f, m1r = -1e30f, l0 = 0.f, l1 = 0.f;
    float acc[8][4];
    #pragma unroll
    for (int ni = 0; ni < 8; ni++)
        #pragma unroll
        for (int r = 0; r < 4; r++) acc[ni][r] = 0.f;

    const int rloc0 = w * 16 + g;
    const int row0  = q0 + rloc0;
    const int row1  = row0 + 8;

    const uint32_t* Qs = fsm;

    #pragma unroll 1
    for (int kt = 0; kt < nt; kt++) {
        if (kt + 1 < nt) { CPA_WAIT1(); } else { CPA_WAIT0(); }
        __syncthreads();
        if (kt + 2 < nt) { ISSUE_KV(kt + 2, (kt + 2) % 3); CPA_COMMIT(); }

        const uint32_t* Ks = fsm + SK_OFF + (kt % 3) * STG_SZ;
        const uint32_t* Vs = Ks + SV_OFF;
        const int k0 = kt * FK;

        float sc[8][4];
        #pragma unroll
        for (int ni = 0; ni < 8; ni++)
            #pragma unroll
            for (int r = 0; r < 4; r++) sc[ni][r] = 0.f;

        #pragma unroll
        for (int kk = 0; kk < 4; kk++) {
            const int off = ((kk * 8 + 2 * tg) ^ gk);
            uint32_t a[4];
            {
                uint2 p0 = *(const uint2*)&Qs[rloc0 * 32 + off];
                uint2 p1 = *(const uint2*)&Qs[(rloc0 + 8) * 32 + off];
                a[0] = p0.x; a[2] = p0.y;
                a[1] = p1.x; a[3] = p1.y;
            }
            #pragma unroll
            for (int ni = 0; ni < 8; ni++) {
                uint2 pb = *(const uint2*)&Ks[(ni * 8 + g) * 32 + off];
                uint32_t b[2] = {pb.x, pb.y};
                mma_fp16(sc[ni], a, b);
            }
        }

        if (kt >= 2 * qt) {
            #pragma unroll
            for (int ni = 0; ni < 8; ni++) {
                const int c = k0 + ni * 8 + 2 * tg;
                if (c     > row0) sc[ni][0] = -1e30f;
                if (c + 1 > row0) sc[ni][1] = -1e30f;
                if (c     > row1) sc[ni][2] = -1e30f;
                if (c + 1 > row1) sc[ni][3] = -1e30f;
            }
        }

        // max-reduce (needs all scores)
        float mx0 = -1e30f, mx1 = -1e30f;
        #pragma unroll
        for (int ni = 0; ni < 8; ni++) {
            mx0 = fmaxf(mx0, fmaxf(sc[ni][0], sc[ni][1]));
            mx1 = fmaxf(mx1, fmaxf(sc[ni][2], sc[ni][3]));
        }
        #pragma unroll
        for (int off = 1; off < 4; off <<= 1) {
            mx0 = fmaxf(mx0, __shfl_xor_sync(0xffffffffu, mx0, off));
            mx1 = fmaxf(mx1, __shfl_xor_sync(0xffffffffu, mx1, off));
        }
        const float mn0 = fmaxf(m0r, mx0);
        const float mn1 = fmaxf(m1r, mx1);
        const float al0 = exp2f(m0r - mn0);
        const float al1 = exp2f(m1r - mn1);

        // rescale acc before GEMM2 accumulation
        #pragma unroll
        for (int ni = 0; ni < 8; ni++) {
            acc[ni][0] *= al0; acc[ni][1] *= al0;
            acc[ni][2] *= al1; acc[ni][3] *= al1;
        }

        // interleaved: per K-chunk kk, exponentiate just the 2 ni-tiles GEMM2
        // needs (8 exp2), pack, then issue its 8 MMAs. exp2 of chunk kk+1 is
        // independent of MMA chunk kk -> MUFU overlaps HMMA.
        float s0 = 0.f, s1 = 0.f;
        #pragma unroll
        for (int kk = 0; kk < 4; kk++) {
            uint32_t a[4];
            #pragma unroll
            for (int u = 0; u < 2; u++) {
                const int nj = 2 * kk + u;
                sc[nj][0] = exp2f(sc[nj][0] - mn0);
                sc[nj][1] = exp2f(sc[nj][1] - mn0);
                sc[nj][2] = exp2f(sc[nj][2] - mn1);
                sc[nj][3] = exp2f(sc[nj][3] - mn1);
                s0 += sc[nj][0] + sc[nj][1];
                s1 += sc[nj][2] + sc[nj][3];
                a[2 * u]     = fpack(sc[nj][0], sc[nj][1]);
                a[2 * u + 1] = fpack(sc[nj][2], sc[nj][3]);
            }
            const int kc = kk * 8;
            #pragma unroll
            for (int ni = 0; ni < 8; ni++) {
                uint32_t b[2];
                const int nb = (ni * 8 + g) * VSTR + kc + tg;
                b[0] = Vs[nb];
                b[1] = Vs[nb + 4];
                mma_fp16(acc[ni], a, b);
            }
        }

        #pragma unroll
        for (int off = 1; off < 4; off <<= 1) {
            s0 += __shfl_xor_sync(0xffffffffu, s0, off);
            s1 += __shfl_xor_sync(0xffffffffu, s1, off);
        }
        l0 = l0 * al0 + s0;
        l1 = l1 * al1 + s1;
        m0r = mn0; m1r = mn1;
    }

    // epilogue: packed fp16 AO with permuted layout (consumed by gemm<1> A)
    const float il0 = 1.f / l0;
    const float il1 = 1.f / l1;
    const int b_ = bh >> 4, nh = bh & 15;
    const int key = row0 & 3;
    #pragma unroll
    for (int ni = 0; ni < 8; ni++) {
        const int c32 = ni * 4 + tg;
        const int cp = nh * 32 + pcol(c32, key);
        AOh[(size_t)(b_ * SS + row0) * HP + cp] =
            fpack(acc[ni][0] * il0, acc[ni][1] * il0);
        AOh[(size_t)(b_ * SS + row1) * HP + cp] =
            fpack(acc[ni][2] * il1, acc[ni][3] * il1);
    }
    #undef ISSUE_KV
}

// ---------------- launcher ---------------------------------------------------
extern "C" void kernel_launch(void* const* d_in, const int* in_sizes, int n_in,
                              void* d_out, int out_size)
{
    (void)in_sizes; (void)n_in; (void)out_size;
    const float* hs = (const float*)d_in[0];
    const float* wq = (const float*)d_in[2];
    const float* wk = (const float*)d_in[3];
    const float* wv = (const float*)d_in[4];
    const float* wo = (const float*)d_in[5];
    const int*  pos = (const int*)d_in[6];
    float* out = (float*)d_out;

    uint32_t *Hh, *Wqh, *Wkh, *Wvh, *Woh, *AOh, *Qh, *Kh, *Vt, *Vh;
    float2* tab;
    cudaGetSymbolAddress((void**)&Hh,  g_Hh);
    cudaGetSymbolAddress((void**)&Wqh, g_Wqh);
    cudaGetSymbolAddress((void**)&Wkh, g_Wkh);
    cudaGetSymbolAddress((void**)&Wvh, g_Wvh);
    cudaGetSymbolAddress((void**)&Woh, g_Woh);
    cudaGetSymbolAddress((void**)&AOh, g_AOh);
    cudaGetSymbolAddress((void**)&Qh,  g_Qh);
    cudaGetSymbolAddress((void**)&Kh,  g_Kh);
    cudaGetSymbolAddress((void**)&Vt,  g_Vt);
    cudaGetSymbolAddress((void**)&Vh,  g_Vh);
    cudaGetSymbolAddress((void**)&tab, g_tab);

    static bool attr_done = false;
    if (!attr_done) {
        cudaFuncSetAttribute(gemm_v8<0>,
                             cudaFuncAttributeMaxDynamicSharedMemorySize, GEMM_SMEM);
        cudaFuncSetAttribute(gemm_v8<1>,
                             cudaFuncAttributeMaxDynamicSharedMemorySize, GEMM_SMEM);
        cudaFuncSetAttribute(flash_fp16,
                             cudaFuncAttributeMaxDynamicSharedMemorySize, FLASH_SMEM);
        attr_done = true;
    }

    pack_all<<<2048, 256>>>(hs, wq, wk, wv, wo, Hh, Wqh, Wkh, Wvh, Woh, tab);

    gemm_v8<0><<<dim3(HH/GTN, MM/GTM, 3), 256, GEMM_SMEM>>>(
        Hh, Wqh, Wkh, Wvh, Qh, Kh, Vt, tab, pos);

    prep_v2<<<dim3(SS/64, BB*NHH), 256>>>(Vt, Vh);

    flash_fp16<<<dim3(SS/FQ, BB*NHH), 256, FLASH_SMEM>>>(Qh, Kh, Vh, AOh);

    gemm_v8<1><<<dim3(HH/GTN, MM/GTM, 1), 256, GEMM_SMEM>>>(
        AOh, Woh, Woh, Woh, out, out, out, tab, pos);
}

// round 15
// speedup vs baseline: 1.1775x; 1.0143x over previous
#include <cuda_runtime.h>
#include <cuda_fp16.h>
#include <cstdint>
#include <math.h>

#define BB 2
#define SS 2048
#define HH 1024
#define NHH 16
#define HDD 64
#define MM (BB*SS)   // 4096
#define HP (HH/2)    // 512 u32 per packed row

// ---------------- scratch (allocation-free: device globals) ----------------
__device__ uint32_t g_Hh [MM*HP];
__device__ uint32_t g_Wqh[HH*HP];
__device__ uint32_t g_Wkh[HH*HP];
__device__ uint32_t g_Wvh[HH*HP];
__device__ uint32_t g_Woh[HH*HP];
__device__ uint32_t g_AOh[MM*HP];
__device__ uint32_t g_Qh[BB*NHH*SS*(HDD/2)];
__device__ uint32_t g_Kh[BB*NHH*SS*(HDD/2)];
__device__ uint32_t g_Vh[BB*NHH*HDD*(SS/2)];   // [bh][d][s-pair], pair-permuted
__device__ float2   g_tab[SS*32];

// ---------------- helpers ----------------------------------------------------
__device__ __forceinline__ uint32_t fpack(float a, float b) {
    __half2 h = __floats2half2_rn(a, b);
    return *reinterpret_cast<uint32_t*>(&h);
}

// layout map: within each 32-u32 block, logical col -> physical col
//   pair perm on bits 0..2:  (tg, tg+4) -> (2tg, 2tg+1)
//   XOR swizzle on bits 3..4 by (row & 3)
__device__ __forceinline__ int pcol(int c32, int key) {
    const int c = c32 & 7;
    return ((c32 & 24) ^ (key << 3)) | (((c & 3) << 1) | ((c >> 2) & 1));
}

__device__ __forceinline__ void mma_fp16(float c[4], const uint32_t a[4], const uint32_t b[2]) {
    asm volatile(
        "mma.sync.aligned.m16n8k16.row.col.f32.f16.f16.f32 "
        "{%0,%1,%2,%3}, {%4,%5,%6,%7}, {%8,%9}, {%0,%1,%2,%3};"
        : "+f"(c[0]), "+f"(c[1]), "+f"(c[2]), "+f"(c[3])
        : "r"(a[0]), "r"(a[1]), "r"(a[2]), "r"(a[3]),
          "r"(b[0]), "r"(b[1]));
}

__device__ __forceinline__ uint32_t smem_u32(const void* p) {
    uint32_t a;
    asm("{ .reg .u64 t; cvta.to.shared.u64 t, %1; cvt.u32.u64 %0, t; }" : "=r"(a) : "l"(p));
    return a;
}

#define CPA16(dst, src) \
    asm volatile("cp.async.cg.shared.global [%0], [%1], 16;" :: "r"(dst), "l"(src))
#define CPA_COMMIT() asm volatile("cp.async.commit_group;" ::: "memory")
#define CPA_WAIT0()  asm volatile("cp.async.wait_group 0;" ::: "memory")
#define CPA_WAIT1()  asm volatile("cp.async.wait_group 1;" ::: "memory")

#define LOG2E 1.4426950408889634f

// ---------------- fused pack + rope table (writes permuted layout) ----------
#define NHS (MM*HP)
#define NWW (HH*HP)
#define NTAB (SS*32)
__global__ void __launch_bounds__(256) pack_all(const float* __restrict__ hs,
                                                const float* __restrict__ wq,
                                                const float* __restrict__ wk,
                                                const float* __restrict__ wv,
                                                const float* __restrict__ wo,
                                                uint32_t* __restrict__ Hh,
                                                uint32_t* __restrict__ Wqh,
                                                uint32_t* __restrict__ Wkh,
                                                uint32_t* __restrict__ Wvh,
                                                uint32_t* __restrict__ Woh,
                                                float2* __restrict__ tab)
{
    const int total = NTAB + NHS + 4 * NWW;
    int i = blockIdx.x * blockDim.x + threadIdx.x;
    const int stride = gridDim.x * blockDim.x;
    for (; i < total; i += stride) {
        if (i < NTAB) {
            const int p = i >> 5, fi = i & 31;
            const float inv = expf(-(float)fi * (logf(10000.0f) / 32.0f));
            float sn, cs;
            sincosf((float)p * inv, &sn, &cs);
            tab[i] = make_float2(cs, sn);
            continue;
        }
        const int t = i - NTAB;
        const float* s; uint32_t* d; int idx;
        if (t < NHS) { s = hs; d = Hh; idx = t; }
        else {
            const int j = t - NHS;
            const int wsel = j >> 19;
            idx = j & (NWW - 1);
            switch (wsel) {
                case 0: s = wq; d = Wqh; break;
                case 1: s = wk; d = Wkh; break;
                case 2: s = wv; d = Wvh; break;
                default: s = wo; d = Woh; break;
            }
        }
        float2 v = ((const float2*)s)[idx];
        const int key = (idx >> 9) & 3;                         // row & 3
        const int out_idx = (idx & ~31) | pcol(idx & 31, key);  // permuted col
        d[out_idx] = fpack(v.x, v.y);
    }
}

// ---------------- GEMM v9: fp16, 128x128 CTA, K-chunk 64, LDS.64 fragments --
// MODE 0, z: 0=Q (RoPE+scale), 1=K (RoPE), 2=V (shuffle-transposed -> Vh)
// MODE 1: row-major fp32 [m*HH + o]
#define GTM 128
#define GTN 128
#define GSTAGE ((GTM + GTN) * 32)       // 8192 u32
static const int GEMM_SMEM = 3 * GSTAGE * (int)sizeof(uint32_t);  // 98304

template<int MODE>
__global__ void __launch_bounds__(256, 2) gemm_v9(const uint32_t* __restrict__ A,
                                                  const uint32_t* __restrict__ B0,
                                                  const uint32_t* __restrict__ B1,
                                                  const uint32_t* __restrict__ B2,
                                                  void* __restrict__ Y0v,
                                                  void* __restrict__ Y1v,
                                                  void* __restrict__ Y2v,
                                                  const float2* __restrict__ tab,
                                                  const int* __restrict__ pos_ids)
{
    extern __shared__ uint32_t sm4[];
    const int z = blockIdx.z;
    const uint32_t* Bp = (z == 0) ? B0 : (z == 1) ? B1 : B2;
    void* Yv           = (z == 0) ? Y0v : (z == 1) ? Y1v : Y2v;

    const int tid  = threadIdx.x;
    const int w    = tid >> 5;
    const int lane = tid & 31;
    const int g    = lane >> 2;
    const int tg   = lane & 3;
    const int gk   = (g & 3) << 3;
    const int wm   = (w & 3) * 32;
    const int wn   = (w >> 2) * 64;
    const int m0   = blockIdx.y * GTM;
    const int n0   = blockIdx.x * GTN;
    const uint32_t sb = smem_u32(sm4);

    #define ISSUE_G(IT, STG)                                                      \
        _Pragma("unroll")                                                         \
        for (int i = 0; i < 8; i++) {                                             \
            const int c = tid + i * 256;                                          \
            const int row = c >> 3, j = c & 7;                                    \
            const uint32_t* src = (row < GTM)                                     \
                ? A  + (size_t)(m0 + row)       * HP + (IT) * 32 + j * 4          \
                : Bp + (size_t)(n0 + row - GTM) * HP + (IT) * 32 + j * 4;         \
            CPA16(sb + ((STG) * GSTAGE + row * 32 + j * 4) * 4, src);             \
        }

    ISSUE_G(0, 0); CPA_COMMIT();
    ISSUE_G(1, 1); CPA_COMMIT();

    float acc[2][8][4];
    #pragma unroll
    for (int mi = 0; mi < 2; mi++)
        #pragma unroll
        for (int ni = 0; ni < 8; ni++)
            #pragma unroll
            for (int r = 0; r < 4; r++) acc[mi][ni][r] = 0.f;

    const int NIT = HP / 32;             // 16
    #pragma unroll 1
    for (int it = 0; it < NIT; it++) {
        if (it < NIT - 1) { CPA_WAIT1(); } else { CPA_WAIT0(); }
        __syncthreads();
        if (it + 2 < NIT) {
            ISSUE_G(it + 2, (it + 2) % 3);
            CPA_COMMIT();
        }

        const uint32_t* cS = sm4 + (it % 3) * GSTAGE;
        const uint32_t* cB = cS + GTM * 32;

        #pragma unroll
        for (int kk = 0; kk < 4; kk++) {
            const int off = ((kk * 8 + 2 * tg) ^ gk);
            uint32_t a[2][4], b[8][2];
            #pragma unroll
            for (int mi = 0; mi < 2; mi++) {
                const int r0 = (wm + 16 * mi + g) * 32 + off;
                uint2 p0 = *(const uint2*)&cS[r0];
                uint2 p1 = *(const uint2*)&cS[r0 + 8 * 32];
                a[mi][0] = p0.x; a[mi][2] = p0.y;
                a[mi][1] = p1.x; a[mi][3] = p1.y;
            }
            #pragma unroll
            for (int ni = 0; ni < 8; ni++) {
                uint2 pb = *(const uint2*)&cB[(wn + 8 * ni + g) * 32 + off];
                b[ni][0] = pb.x; b[ni][1] = pb.y;
            }
            #pragma unroll
            for (int mi = 0; mi < 2; mi++)
                #pragma unroll
                for (int ni = 0; ni < 8; ni++)
                    mma_fp16(acc[mi][ni], a[mi], b[ni]);
        }
    }

    if (MODE == 0) {
        uint32_t* Yh = (uint32_t*)Yv;
        if (z < 2) {
            const int nh = (n0 + wn) >> 6;
            const float qsc = (z == 0) ? (0.125f * LOG2E) : 1.0f;
            #pragma unroll
            for (int mi = 0; mi < 2; mi++) {
                #pragma unroll
                for (int half = 0; half < 2; half++) {
                    const int row = m0 + wm + 16 * mi + g + 8 * half;
                    const int k0  = 2 * half;
                    const int b_  = row >> 11;
                    const int s   = row & (SS - 1);
                    const int key = row & 3;
                    const size_t ob = ((size_t)(b_ * NHH + nh) * SS + s) * 32;
                    int p = pos_ids[b_ * SS + s];
                    p = min(max(p, 0), SS - 1);
                    const float2* tb = tab + p * 32;
                    #pragma unroll
                    for (int ni = 0; ni < 4; ni++) {
                        const int i0 = 8 * ni + 2 * tg;
                        const float2 t0 = tb[i0];
                        const float2 t1 = tb[i0 + 1];
                        const float lo0 = acc[mi][ni][k0],     lo1 = acc[mi][ni][k0 + 1];
                        const float hi0 = acc[mi][ni + 4][k0], hi1 = acc[mi][ni + 4][k0 + 1];
                        const float nl0 = (lo0 * t0.x - hi0 * t0.y) * qsc;
                        const float nl1 = (lo1 * t1.x - hi1 * t1.y) * qsc;
                        const float nh0 = (hi0 * t0.x + lo0 * t0.y) * qsc;
                        const float nh1 = (hi1 * t1.x + lo1 * t1.y) * qsc;
                        const int c1 = 4 * ni + tg;
                        const int c2 = 16 + 4 * ni + tg;
                        Yh[ob + pcol(c1, key)] = fpack(nl0, nl1);
                        Yh[ob + pcol(c2, key)] = fpack(nh0, nh1);
                    }
                }
            }
        } else {
            // V: register-only shuffle transpose -> Vh [bh][d][s-pair],
            // pair-permuted within each 8-u32 group for flash LDS.64.
            const int b_    = m0 >> 11;
            const int sbase = (m0 & (SS - 1)) >> 1;
            const int e     = g >> 1;
            const int dpar  = g & 1;
            const bool geven = (dpar == 0);
            #pragma unroll
            for (int mi = 0; mi < 2; mi++) {
                #pragma unroll
                for (int half = 0; half < 2; half++) {
                    const int k0  = 2 * half;
                    const int Wp  = wm + 16 * mi + 8 * half;
                    const int spl = (Wp >> 1) + e;           // logical s-pair 0..63
                    const int c7  = spl & 7;
                    const int spp = (spl & ~7) | ((c7 & 3) << 1) | (c7 >> 2);
                    #pragma unroll
                    for (int ni = 0; ni < 8; ni++) {
                        const uint32_t pk = fpack(acc[mi][ni][k0], acc[mi][ni][k0 + 1]);
                        const uint32_t q  = __shfl_xor_sync(0xffffffffu, pk, 4);
                        const uint32_t lo = geven ? pk : q;   // even s row
                        const uint32_t hi = geven ? q  : pk;  // odd  s row
                        const uint32_t out = __byte_perm(lo, hi, dpar ? 0x7632 : 0x5410);
                        const int dcol = wn + 8 * ni + 2 * tg + dpar;
                        const int nh   = (n0 + dcol) >> 6;
                        const int d    = dcol & 63;
                        Yh[((size_t)(b_ * NHH + nh) * HDD + d) * (SS / 2) + sbase + spp] = out;
                    }
                }
            }
        }
    } else {
        float* Y = (float*)Yv;
        #pragma unroll
        for (int mi = 0; mi < 2; mi++) {
            #pragma unroll
            for (int ni = 0; ni < 8; ni++) {
                const int row = m0 + wm + 16 * mi + g;
                const int col = n0 + wn + 8 * ni + 2 * tg;
                *(float2*)&Y[(size_t)row * HH + col] =
                    make_float2(acc[mi][ni][0], acc[mi][ni][1]);
                *(float2*)&Y[(size_t)(row + 8) * HH + col] =
                    make_float2(acc[mi][ni][2], acc[mi][ni][3]);
            }
        }
    }
    #undef ISSUE_G
}

// ---------------- flash attention: fp16 MMA, all-LDS.64 fragments -----------
#define FQ 128
#define FK 64
#define VSTR 36
#define SQ_OFF 0
#define SK_OFF (FQ * 32)                 // 4096
#define SV_OFF (FK * 32)                 // 2048
#define STG_SZ (FK * 32 + FK * VSTR)     // 4352 u32
static const int FLASH_SMEM = (FQ * 32 + 3 * STG_SZ) * (int)sizeof(uint32_t);  // 68608

__global__ void __launch_bounds__(256, 2) flash_fp16(const uint32_t* __restrict__ Qh,
                                                     const uint32_t* __restrict__ Kh,
                                                     const uint32_t* __restrict__ Vh,
                                                     uint32_t* __restrict__ AOh)
{
    extern __shared__ uint32_t fsm[];
    const uint32_t sb = smem_u32(fsm);

    const int tid  = threadIdx.x;
    const int w    = tid >> 5;
    const int lane = tid & 31;
    const int g    = lane >> 2;
    const int tg   = lane & 3;
    const int gk   = (g & 3) << 3;
    const int bh   = blockIdx.y;
    const int qt   = (int)(gridDim.x - 1) - (int)blockIdx.x;
    const int q0   = qt * FQ;

    const uint32_t* qsrc = Qh + ((size_t)bh * SS + q0) * 32;
    const uint32_t* ksrc = Kh + (size_t)bh * SS * 32;
    const uint32_t* vsrc = Vh + (size_t)bh * HDD * (SS / 2);

    const int nt = 2 * qt + 2;

    #define ISSUE_KV(KT, STG)                                                     \
        {                                                                         \
            _Pragma("unroll")                                                     \
            for (int i = 0; i < 2; i++) {                                         \
                const int c = tid + i * 256;                                      \
                const int row = c >> 3, j = c & 7;                                \
                CPA16(sb + (SK_OFF + (STG) * STG_SZ + row * 32 + j * 4) * 4,      \
                      ksrc + ((size_t)(KT) * FK + row) * 32 + j * 4);             \
            }                                                                     \
            _Pragma("unroll")                                                     \
            for (int i = 0; i < 2; i++) {                                         \
                const int c = tid + i * 256;                                      \
                const int d = c >> 3, j = c & 7;                                  \
                CPA16(sb + (SK_OFF + (STG) * STG_SZ + SV_OFF + d * VSTR + j * 4) * 4, \
                      vsrc + (size_t)d * (SS / 2) + (KT) * 32 + j * 4);           \
            }                                                                     \
        }

    #pragma unroll
    for (int i = 0; i < 4; i++) {
        const int c = tid + i * 256;
        const int row = c >> 3, j = c & 7;
        CPA16(sb + (SQ_OFF + row * 32 + j * 4) * 4, qsrc + (size_t)row * 32 + j * 4);
    }
    ISSUE_KV(0, 0);
    CPA_COMMIT();
    if (nt > 1) { ISSUE_KV(1, 1); CPA_COMMIT(); }

    float m0r = -1e30f, m1r = -1e30f, l0 = 0.f, l1 = 0.f;
    float acc[8][4];
    #pragma unroll
    for (int ni = 0; ni < 8; ni++)
        #pragma unroll
        for (int r = 0; r < 4; r++) acc[ni][r] = 0.f;

    const int rloc0 = w * 16 + g;
    const int row0  = q0 + rloc0;
    const int row1  = row0 + 8;

    const uint32_t* Qs = fsm;

    #pragma unroll 1
    for (int kt = 0; kt < nt; kt++) {
        if (kt + 1 < nt) { CPA_WAIT1(); } else { CPA_WAIT0(); }
        __syncthreads();
        if (kt + 2 < nt) { ISSUE_KV(kt + 2, (kt + 2) % 3); CPA_COMMIT(); }

        const uint32_t* Ks = fsm + SK_OFF + (kt % 3) * STG_SZ;
        const uint32_t* Vs = Ks + SV_OFF;
        const int k0 = kt * FK;

        float sc[8][4];
        #pragma unroll
        for (int ni = 0; ni < 8; ni++)
            #pragma unroll
            for (int r = 0; r < 4; r++) sc[ni][r] = 0.f;

        #pragma unroll
        for (int kk = 0; kk < 4; kk++) {
            const int off = ((kk * 8 + 2 * tg) ^ gk);
            uint32_t a[4];
            {
                uint2 p0 = *(const uint2*)&Qs[rloc0 * 32 + off];
                uint2 p1 = *(const uint2*)&Qs[(rloc0 + 8) * 32 + off];
                a[0] = p0.x; a[2] = p0.y;
                a[1] = p1.x; a[3] = p1.y;
            }
            #pragma unroll
            for (int ni = 0; ni < 8; ni++) {
                uint2 pb = *(const uint2*)&Ks[(ni * 8 + g) * 32 + off];
                uint32_t b[2] = {pb.x, pb.y};
                mma_fp16(sc[ni], a, b);
            }
        }

        if (kt >= 2 * qt) {
            #pragma unroll
            for (int ni = 0; ni < 8; ni++) {
                const int c = k0 + ni * 8 + 2 * tg;
                if (c     > row0) sc[ni][0] = -1e30f;
                if (c + 1 > row0) sc[ni][1] = -1e30f;
                if (c     > row1) sc[ni][2] = -1e30f;
                if (c + 1 > row1) sc[ni][3] = -1e30f;
            }
        }

        // max-reduce
        float mx0 = -1e30f, mx1 = -1e30f;
        #pragma unroll
        for (int ni = 0; ni < 8; ni++) {
            mx0 = fmaxf(mx0, fmaxf(sc[ni][0], sc[ni][1]));
            mx1 = fmaxf(mx1, fmaxf(sc[ni][2], sc[ni][3]));
        }
        #pragma unroll
        for (int off = 1; off < 4; off <<= 1) {
            mx0 = fmaxf(mx0, __shfl_xor_sync(0xffffffffu, mx0, off));
            mx1 = fmaxf(mx1, __shfl_xor_sync(0xffffffffu, mx1, off));
        }
        const float mn0 = fmaxf(m0r, mx0);
        const float mn1 = fmaxf(m1r, mx1);
        const float al0 = exp2f(m0r - mn0);
        const float al1 = exp2f(m1r - mn1);

        #pragma unroll
        for (int ni = 0; ni < 8; ni++) {
            acc[ni][0] *= al0; acc[ni][1] *= al0;
            acc[ni][2] *= al1; acc[ni][3] *= al1;
        }

        // interleaved exp2 + GEMM2 (V loads are LDS.64 via pair-permuted layout)
        float s0 = 0.f, s1 = 0.f;
        #pragma unroll
        for (int kk = 0; kk < 4; kk++) {
            uint32_t a[4];
            #pragma unroll
            for (int u = 0; u < 2; u++) {
                const int nj = 2 * kk + u;
                sc[nj][0] = exp2f(sc[nj][0] - mn0);
                sc[nj][1] = exp2f(sc[nj][1] - mn0);
                sc[nj][2] = exp2f(sc[nj][2] - mn1);
                sc[nj][3] = exp2f(sc[nj][3] - mn1);
                s0 += sc[nj][0] + sc[nj][1];
                s1 += sc[nj][2] + sc[nj][3];
                a[2 * u]     = fpack(sc[nj][0], sc[nj][1]);
                a[2 * u + 1] = fpack(sc[nj][2], sc[nj][3]);
            }
            const int kc = kk * 8;
            #pragma unroll
            for (int ni = 0; ni < 8; ni++) {
                uint2 pv = *(const uint2*)&Vs[(ni * 8 + g) * VSTR + kc + 2 * tg];
                uint32_t b[2] = {pv.x, pv.y};
                mma_fp16(acc[ni], a, b);
            }
        }

        #pragma unroll
        for (int off = 1; off < 4; off <<= 1) {
            s0 += __shfl_xor_sync(0xffffffffu, s0, off);
            s1 += __shfl_xor_sync(0xffffffffu, s1, off);
        }
        l0 = l0 * al0 + s0;
        l1 = l1 * al1 + s1;
        m0r = mn0; m1r = mn1;
    }

    // epilogue: packed fp16 AO with permuted layout (consumed by gemm<1> A)
    const float il0 = 1.f / l0;
    const float il1 = 1.f / l1;
    const int b_ = bh >> 4, nh = bh & 15;
    const int key = row0 & 3;
    #pragma unroll
    for (int ni = 0; ni < 8; ni++) {
        const int c32 = ni * 4 + tg;
        const int cp = nh * 32 + pcol(c32, key);
        AOh[(size_t)(b_ * SS + row0) * HP + cp] =
            fpack(acc[ni][0] * il0, acc[ni][1] * il0);
        AOh[(size_t)(b_ * SS + row1) * HP + cp] =
            fpack(acc[ni][2] * il1, acc[ni][3] * il1);
    }
    #undef ISSUE_KV
}

// ---------------- launcher ---------------------------------------------------
extern "C" void kernel_launch(void* const* d_in, const int* in_sizes, int n_in,
                              void* d_out, int out_size)
{
    (void)in_sizes; (void)n_in; (void)out_size;
    const float* hs = (const float*)d_in[0];
    const float* wq = (const float*)d_in[2];
    const float* wk = (const float*)d_in[3];
    const float* wv = (const float*)d_in[4];
    const float* wo = (const float*)d_in[5];
    const int*  pos = (const int*)d_in[6];
    float* out = (float*)d_out;

    uint32_t *Hh, *Wqh, *Wkh, *Wvh, *Woh, *AOh, *Qh, *Kh, *Vh;
    float2* tab;
    cudaGetSymbolAddress((void**)&Hh,  g_Hh);
    cudaGetSymbolAddress((void**)&Wqh, g_Wqh);
    cudaGetSymbolAddress((void**)&Wkh, g_Wkh);
    cudaGetSymbolAddress((void**)&Wvh, g_Wvh);
    cudaGetSymbolAddress((void**)&Woh, g_Woh);
    cudaGetSymbolAddress((void**)&AOh, g_AOh);
    cudaGetSymbolAddress((void**)&Qh,  g_Qh);
    cudaGetSymbolAddress((void**)&Kh,  g_Kh);
    cudaGetSymbolAddress((void**)&Vh,  g_Vh);
    cudaGetSymbolAddress((void**)&tab, g_tab);

    static bool attr_done = false;
    if (!attr_done) {
        cudaFuncSetAttribute(gemm_v9<0>,
                             cudaFuncAttributeMaxDynamicSharedMemorySize, GEMM_SMEM);
        cudaFuncSetAttribute(gemm_v9<1>,
                             cudaFuncAttributeMaxDynamicSharedMemorySize, GEMM_SMEM);
        cudaFuncSetAttribute(flash_fp16,
                             cudaFuncAttributeMaxDynamicSharedMemorySize, FLASH_SMEM);
        attr_done = true;
    }

    pack_all<<<2048, 256>>>(hs, wq, wk, wv, wo, Hh, Wqh, Wkh, Wvh, Woh, tab);

    gemm_v9<0><<<dim3(HH/GTN, MM/GTM, 3), 256, GEMM_SMEM>>>(
        Hh, Wqh, Wkh, Wvh, Qh, Kh, Vh, tab, pos);

    flash_fp16<<<dim3(SS/FQ, BB*NHH), 256, FLASH_SMEM>>>(Qh, Kh, Vh, AOh);

    gemm_v9<1><<<dim3(HH/GTN, MM/GTM, 1), 256, GEMM_SMEM>>>(
        AOh, Woh, Woh, Woh, out, out, out, tab, pos);
}

// round 16
// speedup vs baseline: 1.2872x; 1.0931x over previous
#include <cuda_runtime.h>
#include <cuda_fp16.h>
#include <cstdint>
#include <math.h>

#define BB 2
#define SS 2048
#define HH 1024
#define NHH 16
#define HDD 64
#define MM (BB*SS)   // 4096
#define HP (HH/2)    // 512 u32 per packed row

// ---------------- scratch (allocation-free: device globals) ----------------
__device__ uint32_t g_Hh [MM*HP];
__device__ uint32_t g_Wqh[HH*HP];
__device__ uint32_t g_Wkh[HH*HP];
__device__ uint32_t g_Wvh[HH*HP];
__device__ uint32_t g_Woh[HH*HP];
__device__ uint32_t g_AOh[MM*HP];
__device__ uint32_t g_Qh[BB*NHH*SS*(HDD/2)];
__device__ uint32_t g_Kh[BB*NHH*SS*(HDD/2)];
__device__ uint32_t g_Vh[BB*NHH*HDD*(SS/2)];   // [bh][d][s-pair], pair-permuted
__device__ float2   g_tab[SS*32];

// ---------------- helpers ----------------------------------------------------
__device__ __forceinline__ uint32_t fpack(float a, float b) {
    __half2 h = __floats2half2_rn(a, b);
    return *reinterpret_cast<uint32_t*>(&h);
}

// layout map: within each 32-u32 block, logical col -> physical col
__device__ __forceinline__ int pcol(int c32, int key) {
    const int c = c32 & 7;
    return ((c32 & 24) ^ (key << 3)) | (((c & 3) << 1) | ((c >> 2) & 1));
}

__device__ __forceinline__ void mma_fp16(float c[4], const uint32_t a[4], const uint32_t b[2]) {
    asm volatile(
        "mma.sync.aligned.m16n8k16.row.col.f32.f16.f16.f32 "
        "{%0,%1,%2,%3}, {%4,%5,%6,%7}, {%8,%9}, {%0,%1,%2,%3};"
        : "+f"(c[0]), "+f"(c[1]), "+f"(c[2]), "+f"(c[3])
        : "r"(a[0]), "r"(a[1]), "r"(a[2]), "r"(a[3]),
          "r"(b[0]), "r"(b[1]));
}

__device__ __forceinline__ uint32_t smem_u32(const void* p) {
    uint32_t a;
    asm("{ .reg .u64 t; cvta.to.shared.u64 t, %1; cvt.u32.u64 %0, t; }" : "=r"(a) : "l"(p));
    return a;
}

#define CPA16(dst, src) \
    asm volatile("cp.async.cg.shared.global [%0], [%1], 16;" :: "r"(dst), "l"(src))
#define CPA_COMMIT() asm volatile("cp.async.commit_group;" ::: "memory")
#define CPA_WAIT0()  asm volatile("cp.async.wait_group 0;" ::: "memory")
#define CPA_WAIT1()  asm volatile("cp.async.wait_group 1;" ::: "memory")

#define LOG2E 1.4426950408889634f

// ---------------- fused pack + rope table (writes permuted layout) ----------
#define NHS (MM*HP)
#define NWW (HH*HP)
#define NTAB (SS*32)
__global__ void __launch_bounds__(256) pack_all(const float* __restrict__ hs,
                                                const float* __restrict__ wq,
                                                const float* __restrict__ wk,
                                                const float* __restrict__ wv,
                                                const float* __restrict__ wo,
                                                uint32_t* __restrict__ Hh,
                                                uint32_t* __restrict__ Wqh,
                                                uint32_t* __restrict__ Wkh,
                                                uint32_t* __restrict__ Wvh,
                                                uint32_t* __restrict__ Woh,
                                                float2* __restrict__ tab)
{
    const int total = NTAB + NHS + 4 * NWW;
    int i = blockIdx.x * blockDim.x + threadIdx.x;
    const int stride = gridDim.x * blockDim.x;
    for (; i < total; i += stride) {
        if (i < NTAB) {
            const int p = i >> 5, fi = i & 31;
            const float inv = expf(-(float)fi * (logf(10000.0f) / 32.0f));
            float sn, cs;
            sincosf((float)p * inv, &sn, &cs);
            tab[i] = make_float2(cs, sn);
            continue;
        }
        const int t = i - NTAB;
        const float* s; uint32_t* d; int idx;
        if (t < NHS) { s = hs; d = Hh; idx = t; }
        else {
            const int j = t - NHS;
            const int wsel = j >> 19;
            idx = j & (NWW - 1);
            switch (wsel) {
                case 0: s = wq; d = Wqh; break;
                case 1: s = wk; d = Wkh; break;
                case 2: s = wv; d = Wvh; break;
                default: s = wo; d = Woh; break;
            }
        }
        float2 v = ((const float2*)s)[idx];
        const int key = (idx >> 9) & 3;
        const int out_idx = (idx & ~31) | pcol(idx & 31, key);
        d[out_idx] = fpack(v.x, v.y);
    }
}

// ---------------- GEMM v9: fp16, 128x128 CTA, K-chunk 64, LDS.64 fragments --
#define GTM 128
#define GTN 128
#define GSTAGE ((GTM + GTN) * 32)       // 8192 u32
static const int GEMM_SMEM = 3 * GSTAGE * (int)sizeof(uint32_t);  // 98304

template<int MODE>
__global__ void __launch_bounds__(256, 2) gemm_v9(const uint32_t* __restrict__ A,
                                                  const uint32_t* __restrict__ B0,
                                                  const uint32_t* __restrict__ B1,
                                                  const uint32_t* __restrict__ B2,
                                                  void* __restrict__ Y0v,
                                                  void* __restrict__ Y1v,
                                                  void* __restrict__ Y2v,
                                                  const float2* __restrict__ tab,
                                                  const int* __restrict__ pos_ids)
{
    extern __shared__ uint32_t sm4[];
    const int z = blockIdx.z;
    const uint32_t* Bp = (z == 0) ? B0 : (z == 1) ? B1 : B2;
    void* Yv           = (z == 0) ? Y0v : (z == 1) ? Y1v : Y2v;

    const int tid  = threadIdx.x;
    const int w    = tid >> 5;
    const int lane = tid & 31;
    const int g    = lane >> 2;
    const int tg   = lane & 3;
    const int gk   = (g & 3) << 3;
    const int wm   = (w & 3) * 32;
    const int wn   = (w >> 2) * 64;
    const int m0   = blockIdx.y * GTM;
    const int n0   = blockIdx.x * GTN;
    const uint32_t sb = smem_u32(sm4);

    #define ISSUE_G(IT, STG)                                                      \
        _Pragma("unroll")                                                         \
        for (int i = 0; i < 8; i++) {                                             \
            const int c = tid + i * 256;                                          \
            const int row = c >> 3, j = c & 7;                                    \
            const uint32_t* src = (row < GTM)                                     \
                ? A  + (size_t)(m0 + row)       * HP + (IT) * 32 + j * 4          \
                : Bp + (size_t)(n0 + row - GTM) * HP + (IT) * 32 + j * 4;         \
            CPA16(sb + ((STG) * GSTAGE + row * 32 + j * 4) * 4, src);             \
        }

    ISSUE_G(0, 0); CPA_COMMIT();
    ISSUE_G(1, 1); CPA_COMMIT();

    float acc[2][8][4];
    #pragma unroll
    for (int mi = 0; mi < 2; mi++)
        #pragma unroll
        for (int ni = 0; ni < 8; ni++)
            #pragma unroll
            for (int r = 0; r < 4; r++) acc[mi][ni][r] = 0.f;

    const int NIT = HP / 32;             // 16
    #pragma unroll 1
    for (int it = 0; it < NIT; it++) {
        if (it < NIT - 1) { CPA_WAIT1(); } else { CPA_WAIT0(); }
        __syncthreads();
        if (it + 2 < NIT) {
            ISSUE_G(it + 2, (it + 2) % 3);
            CPA_COMMIT();
        }

        const uint32_t* cS = sm4 + (it % 3) * GSTAGE;
        const uint32_t* cB = cS + GTM * 32;

        #pragma unroll
        for (int kk = 0; kk < 4; kk++) {
            const int off = ((kk * 8 + 2 * tg) ^ gk);
            uint32_t a[2][4], b[8][2];
            #pragma unroll
            for (int mi = 0; mi < 2; mi++) {
                const int r0 = (wm + 16 * mi + g) * 32 + off;
                uint2 p0 = *(const uint2*)&cS[r0];
                uint2 p1 = *(const uint2*)&cS[r0 + 8 * 32];
                a[mi][0] = p0.x; a[mi][2] = p0.y;
                a[mi][1] = p1.x; a[mi][3] = p1.y;
            }
            #pragma unroll
            for (int ni = 0; ni < 8; ni++) {
                uint2 pb = *(const uint2*)&cB[(wn + 8 * ni + g) * 32 + off];
                b[ni][0] = pb.x; b[ni][1] = pb.y;
            }
            #pragma unroll
            for (int mi = 0; mi < 2; mi++)
                #pragma unroll
                for (int ni = 0; ni < 8; ni++)
                    mma_fp16(acc[mi][ni], a[mi], b[ni]);
        }
    }

    if (MODE == 0) {
        uint32_t* Yh = (uint32_t*)Yv;
        if (z < 2) {
            const int nh = (n0 + wn) >> 6;
            const float qsc = (z == 0) ? (0.125f * LOG2E) : 1.0f;
            #pragma unroll
            for (int mi = 0; mi < 2; mi++) {
                #pragma unroll
                for (int half = 0; half < 2; half++) {
                    const int row = m0 + wm + 16 * mi + g + 8 * half;
                    const int k0  = 2 * half;
                    const int b_  = row >> 11;
                    const int s   = row & (SS - 1);
                    const int key = row & 3;
                    const size_t ob = ((size_t)(b_ * NHH + nh) * SS + s) * 32;
                    int p = pos_ids[b_ * SS + s];
                    p = min(max(p, 0), SS - 1);
                    const float2* tb = tab + p * 32;
                    #pragma unroll
                    for (int ni = 0; ni < 4; ni++) {
                        const int i0 = 8 * ni + 2 * tg;
                        const float2 t0 = tb[i0];
                        const float2 t1 = tb[i0 + 1];
                        const float lo0 = acc[mi][ni][k0],     lo1 = acc[mi][ni][k0 + 1];
                        const float hi0 = acc[mi][ni + 4][k0], hi1 = acc[mi][ni + 4][k0 + 1];
                        const float nl0 = (lo0 * t0.x - hi0 * t0.y) * qsc;
                        const float nl1 = (lo1 * t1.x - hi1 * t1.y) * qsc;
                        const float nh0 = (hi0 * t0.x + lo0 * t0.y) * qsc;
                        const float nh1 = (hi1 * t1.x + lo1 * t1.y) * qsc;
                        const int c1 = 4 * ni + tg;
                        const int c2 = 16 + 4 * ni + tg;
                        Yh[ob + pcol(c1, key)] = fpack(nl0, nl1);
                        Yh[ob + pcol(c2, key)] = fpack(nh0, nh1);
                    }
                }
            }
        } else {
            // V: register-only shuffle transpose -> Vh [bh][d][s-pair], pair-permuted
            const int b_    = m0 >> 11;
            const int sbase = (m0 & (SS - 1)) >> 1;
            const int e     = g >> 1;
            const int dpar  = g & 1;
            const bool geven = (dpar == 0);
            #pragma unroll
            for (int mi = 0; mi < 2; mi++) {
                #pragma unroll
                for (int half = 0; half < 2; half++) {
                    const int k0  = 2 * half;
                    const int Wp  = wm + 16 * mi + 8 * half;
                    const int spl = (Wp >> 1) + e;
                    const int c7  = spl & 7;
                    const int spp = (spl & ~7) | ((c7 & 3) << 1) | (c7 >> 2);
                    #pragma unroll
                    for (int ni = 0; ni < 8; ni++) {
                        const uint32_t pk = fpack(acc[mi][ni][k0], acc[mi][ni][k0 + 1]);
                        const uint32_t q  = __shfl_xor_sync(0xffffffffu, pk, 4);
                        const uint32_t lo = geven ? pk : q;
                        const uint32_t hi = geven ? q  : pk;
                        const uint32_t out = __byte_perm(lo, hi, dpar ? 0x7632 : 0x5410);
                        const int dcol = wn + 8 * ni + 2 * tg + dpar;
                        const int nh   = (n0 + dcol) >> 6;
                        const int d    = dcol & 63;
                        Yh[((size_t)(b_ * NHH + nh) * HDD + d) * (SS / 2) + sbase + spp] = out;
                    }
                }
            }
        }
    } else {
        float* Y = (float*)Yv;
        #pragma unroll
        for (int mi = 0; mi < 2; mi++) {
            #pragma unroll
            for (int ni = 0; ni < 8; ni++) {
                const int row = m0 + wm + 16 * mi + g;
                const int col = n0 + wn + 8 * ni + 2 * tg;
                *(float2*)&Y[(size_t)row * HH + col] =
                    make_float2(acc[mi][ni][0], acc[mi][ni][1]);
                *(float2*)&Y[(size_t)(row + 8) * HH + col] =
                    make_float2(acc[mi][ni][2], acc[mi][ni][3]);
            }
        }
    }
    #undef ISSUE_G
}

// ---------------- flash attention: fp16 MMA, paired-diagonal balance --------
// grid (8, 32): CTA bx handles q-tiles {15-bx, bx} -> uniform 34 K-tiles/CTA,
// 256 CTAs = single wave.
#define FQ 128
#define FK 64
#define VSTR 36
#define SQ_OFF 0
#define SK_OFF (FQ * 32)                 // 4096
#define SV_OFF (FK * 32)                 // 2048
#define STG_SZ (FK * 32 + FK * VSTR)     // 4352 u32
#define NQT (SS / FQ)                    // 16
static const int FLASH_SMEM = (FQ * 32 + 3 * STG_SZ) * (int)sizeof(uint32_t);  // 68608

__global__ void __launch_bounds__(256, 2) flash_fp16(const uint32_t* __restrict__ Qh,
                                                     const uint32_t* __restrict__ Kh,
                                                     const uint32_t* __restrict__ Vh,
                                                     uint32_t* __restrict__ AOh)
{
    extern __shared__ uint32_t fsm[];
    const uint32_t sb = smem_u32(fsm);

    const int tid  = threadIdx.x;
    const int w    = tid >> 5;
    const int lane = tid & 31;
    const int g    = lane >> 2;
    const int tg   = lane & 3;
    const int gk   = (g & 3) << 3;
    const int bh   = blockIdx.y;

    const uint32_t* ksrc = Kh + (size_t)bh * SS * 32;
    const uint32_t* vsrc = Vh + (size_t)bh * HDD * (SS / 2);
    const uint32_t* Qs = fsm;
    const int rloc0 = w * 16 + g;
    const int b_ = bh >> 4, nh = bh & 15;

    #define ISSUE_KV(KT, STG)                                                     \
        {                                                                         \
            _Pragma("unroll")                                                     \
            for (int i = 0; i < 2; i++) {                                         \
                const int c = tid + i * 256;                                      \
                const int row = c >> 3, j = c & 7;                                \
                CPA16(sb + (SK_OFF + (STG) * STG_SZ + row * 32 + j * 4) * 4,      \
                      ksrc + ((size_t)(KT) * FK + row) * 32 + j * 4);             \
            }                                                                     \
            _Pragma("unroll")                                                     \
            for (int i = 0; i < 2; i++) {                                         \
                const int c = tid + i * 256;                                      \
                const int d = c >> 3, j = c & 7;                                  \
                CPA16(sb + (SK_OFF + (STG) * STG_SZ + SV_OFF + d * VSTR + j * 4) * 4, \
                      vsrc + (size_t)d * (SS / 2) + (KT) * 32 + j * 4);           \
            }                                                                     \
        }

    #pragma unroll 1
    for (int hv = 0; hv < 2; hv++) {
        const int qt = hv ? (int)blockIdx.x : (NQT - 1 - (int)blockIdx.x);
        const int q0 = qt * FQ;
        const uint32_t* qsrc = Qh + ((size_t)bh * SS + q0) * 32;
        const int nt = 2 * qt + 2;

        if (hv) __syncthreads();   // smem reads of pass 0 done before restaging

        #pragma unroll
        for (int i = 0; i < 4; i++) {
            const int c = tid + i * 256;
            const int row = c >> 3, j = c & 7;
            CPA16(sb + (SQ_OFF + row * 32 + j * 4) * 4, qsrc + (size_t)row * 32 + j * 4);
        }
        ISSUE_KV(0, 0);
        CPA_COMMIT();
        if (nt > 1) { ISSUE_KV(1, 1); CPA_COMMIT(); }

        float m0r = -1e30f, m1r = -1e30f, l0 = 0.f, l1 = 0.f;
        float acc[8][4];
        #pragma unroll
        for (int ni = 0; ni < 8; ni++)
            #pragma unroll
            for (int r = 0; r < 4; r++) acc[ni][r] = 0.f;

        const int row0 = q0 + rloc0;
        const int row1 = row0 + 8;

        #pragma unroll 1
        for (int kt = 0; kt < nt; kt++) {
            if (kt + 1 < nt) { CPA_WAIT1(); } else { CPA_WAIT0(); }
            __syncthreads();
            if (kt + 2 < nt) { ISSUE_KV(kt + 2, (kt + 2) % 3); CPA_COMMIT(); }

            const uint32_t* Ks = fsm + SK_OFF + (kt % 3) * STG_SZ;
            const uint32_t* Vs = Ks + SV_OFF;
            const int k0 = kt * FK;

            float sc[8][4];
            #pragma unroll
            for (int ni = 0; ni < 8; ni++)
                #pragma unroll
                for (int r = 0; r < 4; r++) sc[ni][r] = 0.f;

            #pragma unroll
            for (int kk = 0; kk < 4; kk++) {
                const int off = ((kk * 8 + 2 * tg) ^ gk);
                uint32_t a[4];
                {
                    uint2 p0 = *(const uint2*)&Qs[rloc0 * 32 + off];
                    uint2 p1 = *(const uint2*)&Qs[(rloc0 + 8) * 32 + off];
                    a[0] = p0.x; a[2] = p0.y;
                    a[1] = p1.x; a[3] = p1.y;
                }
                #pragma unroll
                for (int ni = 0; ni < 8; ni++) {
                    uint2 pb = *(const uint2*)&Ks[(ni * 8 + g) * 32 + off];
                    uint32_t b[2] = {pb.x, pb.y};
                    mma_fp16(sc[ni], a, b);
                }
            }

            if (kt >= 2 * qt) {
                #pragma unroll
                for (int ni = 0; ni < 8; ni++) {
                    const int c = k0 + ni * 8 + 2 * tg;
                    if (c     > row0) sc[ni][0] = -1e30f;
                    if (c + 1 > row0) sc[ni][1] = -1e30f;
                    if (c     > row1) sc[ni][2] = -1e30f;
                    if (c + 1 > row1) sc[ni][3] = -1e30f;
                }
            }

            float mx0 = -1e30f, mx1 = -1e30f;
            #pragma unroll
            for (int ni = 0; ni < 8; ni++) {
                mx0 = fmaxf(mx0, fmaxf(sc[ni][0], sc[ni][1]));
                mx1 = fmaxf(mx1, fmaxf(sc[ni][2], sc[ni][3]));
            }
            #pragma unroll
            for (int off = 1; off < 4; off <<= 1) {
                mx0 = fmaxf(mx0, __shfl_xor_sync(0xffffffffu, mx0, off));
                mx1 = fmaxf(mx1, __shfl_xor_sync(0xffffffffu, mx1, off));
            }
            const float mn0 = fmaxf(m0r, mx0);
            const float mn1 = fmaxf(m1r, mx1);
            const float al0 = exp2f(m0r - mn0);
            const float al1 = exp2f(m1r - mn1);

            #pragma unroll
            for (int ni = 0; ni < 8; ni++) {
                acc[ni][0] *= al0; acc[ni][1] *= al0;
                acc[ni][2] *= al1; acc[ni][3] *= al1;
            }

            float s0 = 0.f, s1 = 0.f;
            #pragma unroll
            for (int kk = 0; kk < 4; kk++) {
                uint32_t a[4];
                #pragma unroll
                for (int u = 0; u < 2; u++) {
                    const int nj = 2 * kk + u;
                    sc[nj][0] = exp2f(sc[nj][0] - mn0);
                    sc[nj][1] = exp2f(sc[nj][1] - mn0);
                    sc[nj][2] = exp2f(sc[nj][2] - mn1);
                    sc[nj][3] = exp2f(sc[nj][3] - mn1);
                    s0 += sc[nj][0] + sc[nj][1];
                    s1 += sc[nj][2] + sc[nj][3];
                    a[2 * u]     = fpack(sc[nj][0], sc[nj][1]);
                    a[2 * u + 1] = fpack(sc[nj][2], sc[nj][3]);
                }
                const int kc = kk * 8;
                #pragma unroll
                for (int ni = 0; ni < 8; ni++) {
                    uint2 pv = *(const uint2*)&Vs[(ni * 8 + g) * VSTR + kc + 2 * tg];
                    uint32_t b[2] = {pv.x, pv.y};
                    mma_fp16(acc[ni], a, b);
                }
            }

            #pragma unroll
            for (int off = 1; off < 4; off <<= 1) {
                s0 += __shfl_xor_sync(0xffffffffu, s0, off);
                s1 += __shfl_xor_sync(0xffffffffu, s1, off);
            }
            l0 = l0 * al0 + s0;
            l1 = l1 * al1 + s1;
            m0r = mn0; m1r = mn1;
        }

        // epilogue: packed fp16 AO with permuted layout
        const float il0 = 1.f / l0;
        const float il1 = 1.f / l1;
        const int key = row0 & 3;
        #pragma unroll
        for (int ni = 0; ni < 8; ni++) {
            const int c32 = ni * 4 + tg;
            const int cp = nh * 32 + pcol(c32, key);
            AOh[(size_t)(b_ * SS + row0) * HP + cp] =
                fpack(acc[ni][0] * il0, acc[ni][1] * il0);
            AOh[(size_t)(b_ * SS + row1) * HP + cp] =
                fpack(acc[ni][2] * il1, acc[ni][3] * il1);
        }
    }
    #undef ISSUE_KV
}

// ---------------- launcher ---------------------------------------------------
extern "C" void kernel_launch(void* const* d_in, const int* in_sizes, int n_in,
                              void* d_out, int out_size)
{
    (void)in_sizes; (void)n_in; (void)out_size;
    const float* hs = (const float*)d_in[0];
    const float* wq = (const float*)d_in[2];
    const float* wk = (const float*)d_in[3];
    const float* wv = (const float*)d_in[4];
    const float* wo = (const float*)d_in[5];
    const int*  pos = (const int*)d_in[6];
    float* out = (float*)d_out;

    uint32_t *Hh, *Wqh, *Wkh, *Wvh, *Woh, *AOh, *Qh, *Kh, *Vh;
    float2* tab;
    cudaGetSymbolAddress((void**)&Hh,  g_Hh);
    cudaGetSymbolAddress((void**)&Wqh, g_Wqh);
    cudaGetSymbolAddress((void**)&Wkh, g_Wkh);
    cudaGetSymbolAddress((void**)&Wvh, g_Wvh);
    cudaGetSymbolAddress((void**)&Woh, g_Woh);
    cudaGetSymbolAddress((void**)&AOh, g_AOh);
    cudaGetSymbolAddress((void**)&Qh,  g_Qh);
    cudaGetSymbolAddress((void**)&Kh,  g_Kh);
    cudaGetSymbolAddress((void**)&Vh,  g_Vh);
    cudaGetSymbolAddress((void**)&tab, g_tab);

    static bool attr_done = false;
    if (!attr_done) {
        cudaFuncSetAttribute(gemm_v9<0>,
                             cudaFuncAttributeMaxDynamicSharedMemorySize, GEMM_SMEM);
        cudaFuncSetAttribute(gemm_v9<1>,
                             cudaFuncAttributeMaxDynamicSharedMemorySize, GEMM_SMEM);
        cudaFuncSetAttribute(flash_fp16,
                             cudaFuncAttributeMaxDynamicSharedMemorySize, FLASH_SMEM);
        attr_done = true;
    }

    pack_all<<<2048, 256>>>(hs, wq, wk, wv, wo, Hh, Wqh, Wkh, Wvh, Woh, tab);

    gemm_v9<0><<<dim3(HH/GTN, MM/GTM, 3), 256, GEMM_SMEM>>>(
        Hh, Wqh, Wkh, Wvh, Qh, Kh, Vh, tab, pos);

    flash_fp16<<<dim3(NQT/2, BB*NHH), 256, FLASH_SMEM>>>(Qh, Kh, Vh, AOh);

    gemm_v9<1><<<dim3(HH/GTN, MM/GTM, 1), 256, GEMM_SMEM>>>(
        AOh, Woh, Woh, Woh, out, out, out, tab, pos);
}

// round 17
// speedup vs baseline: 1.4526x; 1.1286x over previous
#include <cuda_runtime.h>
#include <cuda_fp16.h>
#include <cstdint>
#include <math.h>

#define BB 2
#define SS 2048
#define HH 1024
#define NHH 16
#define HDD 64
#define MM (BB*SS)   // 4096
#define HP (HH/2)    // 512 u32 per packed row

// ---------------- scratch (allocation-free: device globals) ----------------
__device__ uint32_t g_Hh [MM*HP];
__device__ uint32_t g_Wqh[HH*HP];
__device__ uint32_t g_Wkh[HH*HP];
__device__ uint32_t g_Wvh[HH*HP];
__device__ uint32_t g_Woh[HH*HP];
__device__ uint32_t g_AOh[MM*HP];
__device__ uint32_t g_Qh[BB*NHH*SS*(HDD/2)];   // permuted layout (flash)
__device__ uint32_t g_Kh[BB*NHH*SS*(HDD/2)];   // permuted layout (flash)
__device__ uint32_t g_Vh[BB*NHH*HDD*(SS/2)];   // [bh][d][s-pair], pair-permuted
__device__ float2   g_tab[SS*32];

// ---------------- helpers ----------------------------------------------------
__device__ __forceinline__ uint32_t fpack(float a, float b) {
    __half2 h = __floats2half2_rn(a, b);
    return *reinterpret_cast<uint32_t*>(&h);
}

// permuted map (Qh/Kh only): pair perm + 2-bit XOR swizzle
__device__ __forceinline__ int pcol(int c32, int key) {
    const int c = c32 & 7;
    return ((c32 & 24) ^ (key << 3)) | (((c & 3) << 1) | ((c >> 2) & 1));
}

__device__ __forceinline__ void mma_fp16(float c[4], const uint32_t a[4], const uint32_t b[2]) {
    asm volatile(
        "mma.sync.aligned.m16n8k16.row.col.f32.f16.f16.f32 "
        "{%0,%1,%2,%3}, {%4,%5,%6,%7}, {%8,%9}, {%0,%1,%2,%3};"
        : "+f"(c[0]), "+f"(c[1]), "+f"(c[2]), "+f"(c[3])
        : "r"(a[0]), "r"(a[1]), "r"(a[2]), "r"(a[3]),
          "r"(b[0]), "r"(b[1]));
}

__device__ __forceinline__ void ldm_x4(uint32_t r[4], uint32_t addr) {
    asm volatile("ldmatrix.sync.aligned.m8n8.x4.shared.b16 {%0,%1,%2,%3}, [%4];"
        : "=r"(r[0]), "=r"(r[1]), "=r"(r[2]), "=r"(r[3]) : "r"(addr));
}

__device__ __forceinline__ uint32_t smem_u32(const void* p) {
    uint32_t a;
    asm("{ .reg .u64 t; cvta.to.shared.u64 t, %1; cvt.u32.u64 %0, t; }" : "=r"(a) : "l"(p));
    return a;
}

#define CPA16(dst, src) \
    asm volatile("cp.async.cg.shared.global [%0], [%1], 16;" :: "r"(dst), "l"(src))
#define CPA_COMMIT() asm volatile("cp.async.commit_group;" ::: "memory")
#define CPA_WAIT0()  asm volatile("cp.async.wait_group 0;" ::: "memory")
#define CPA_WAIT1()  asm volatile("cp.async.wait_group 1;" ::: "memory")

#define LOG2E 1.4426950408889634f

// ---------------- fused pack + rope table (canonical 3-bit swizzle) ---------
// canonical map: u32 col c in 32-group -> ((c>>2) ^ (row&7))<<2 | (c&3)
#define NHS (MM*HP)
#define NWW (HH*HP)
#define NTAB (SS*32)
#define NGHS (NHS/2)        // 1M granules (2 u32 each)
#define NGW  (NWW/2)        // 256K = 1<<18
__global__ void __launch_bounds__(256) pack_all(const float* __restrict__ hs,
                                                const float* __restrict__ wq,
                                                const float* __restrict__ wk,
                                                const float* __restrict__ wv,
                                                const float* __restrict__ wo,
                                                uint32_t* __restrict__ Hh,
                                                uint32_t* __restrict__ Wqh,
                                                uint32_t* __restrict__ Wkh,
                                                uint32_t* __restrict__ Wvh,
                                                uint32_t* __restrict__ Woh,
                                                float2* __restrict__ tab)
{
    const int total = NTAB + NGHS + 4 * NGW;
    int i = blockIdx.x * blockDim.x + threadIdx.x;
    const int stride = gridDim.x * blockDim.x;
    for (; i < total; i += stride) {
        if (i < NTAB) {
            const int p = i >> 5, fi = i & 31;
            const float inv = expf(-(float)fi * (logf(10000.0f) / 32.0f));
            float sn, cs;
            sincosf((float)p * inv, &sn, &cs);
            tab[i] = make_float2(cs, sn);
            continue;
        }
        const int t = i - NTAB;
        const float* s; uint32_t* d; int gi;
        if (t < NGHS) { s = hs; d = Hh; gi = t; }
        else {
            const int j = t - NGHS;
            const int wsel = j >> 18;
            gi = j & (NGW - 1);
            switch (wsel) {
                case 0: s = wq; d = Wqh; break;
                case 1: s = wk; d = Wkh; break;
                case 2: s = wv; d = Wvh; break;
                default: s = wo; d = Woh; break;
            }
        }
        const float4 v = ((const float4*)s)[gi];
        const int idx2 = gi * 2;                  // u32 index (even)
        const int key  = (idx2 >> 9) & 7;         // row & 7
        const int c    = idx2 & 31;
        const int out  = (idx2 & ~31) | ((((c >> 2) ^ key) << 2) | (c & 3));
        *(uint2*)&d[out] = make_uint2(fpack(v.x, v.y), fpack(v.z, v.w));
    }
}

// ---------------- GEMM v10: fp16, 128x128 CTA, K-chunk 64, ldmatrix ---------
// Operands in canonical layout + 3-bit row-XOR chunk swizzle (baked globally,
// stage copied verbatim). Fragments via ldmatrix.x4: conflict-free.
// MODE 0, z: 0=Q (RoPE+scale, permuted out), 1=K (RoPE, permuted out),
//           2=V (shuffle-transposed -> Vh)
// MODE 1: row-major fp32 [m*HH + o]
#define GTM 128
#define GTN 128
#define GSTAGE ((GTM + GTN) * 32)       // 8192 u32
static const int GEMM_SMEM = 3 * GSTAGE * (int)sizeof(uint32_t);  // 98304

template<int MODE>
__global__ void __launch_bounds__(256, 2) gemm_v10(const uint32_t* __restrict__ A,
                                                   const uint32_t* __restrict__ B0,
                                                   const uint32_t* __restrict__ B1,
                                                   const uint32_t* __restrict__ B2,
                                                   void* __restrict__ Y0v,
                                                   void* __restrict__ Y1v,
                                                   void* __restrict__ Y2v,
                                                   const float2* __restrict__ tab,
                                                   const int* __restrict__ pos_ids)
{
    extern __shared__ uint32_t sm4[];
    const int z = blockIdx.z;
    const uint32_t* Bp = (z == 0) ? B0 : (z == 1) ? B1 : B2;
    void* Yv           = (z == 0) ? Y0v : (z == 1) ? Y1v : Y2v;

    const int tid  = threadIdx.x;
    const int w    = tid >> 5;
    const int lane = tid & 31;
    const int g    = lane >> 2;
    const int tg   = lane & 3;
    const int wm   = (w & 3) * 32;
    const int wn   = (w >> 2) * 64;
    const int m0   = blockIdx.y * GTM;
    const int n0   = blockIdx.x * GTN;
    const uint32_t sb = smem_u32(sm4);

    // ldmatrix addressing precompute (byte offsets within a stage)
    const int l7  = lane & 7;
    const int sel = lane >> 3;                 // 0..3
    int aRB[2], bRB[4], jAo[4], jBo[4];
    #pragma unroll
    for (int mi = 0; mi < 2; mi++)
        aRB[mi] = (wm + 16 * mi + l7 + (sel & 1) * 8) * 128;
    #pragma unroll
    for (int p = 0; p < 4; p++)
        bRB[p] = (GTM + wn + 16 * p + (sel >> 1) * 8 + l7) * 128;
    #pragma unroll
    for (int kk = 0; kk < 4; kk++) {
        jAo[kk] = (((2 * kk + (sel >> 1)) ^ l7) << 4);
        jBo[kk] = (((2 * kk + (sel & 1)) ^ l7) << 4);
    }

    #define ISSUE_G(IT, STG)                                                      \
        _Pragma("unroll")                                                         \
        for (int i = 0; i < 8; i++) {                                             \
            const int c = tid + i * 256;                                          \
            const int row = c >> 3, j = c & 7;                                    \
            const uint32_t* src = (row < GTM)                                     \
                ? A  + (size_t)(m0 + row)       * HP + (IT) * 32 + j * 4          \
                : Bp + (size_t)(n0 + row - GTM) * HP + (IT) * 32 + j * 4;         \
            CPA16(sb + ((STG) * GSTAGE + row * 32 + j * 4) * 4, src);             \
        }

    ISSUE_G(0, 0); CPA_COMMIT();
    ISSUE_G(1, 1); CPA_COMMIT();

    float acc[2][8][4];
    #pragma unroll
    for (int mi = 0; mi < 2; mi++)
        #pragma unroll
        for (int ni = 0; ni < 8; ni++)
            #pragma unroll
            for (int r = 0; r < 4; r++) acc[mi][ni][r] = 0.f;

    const int NIT = HP / 32;             // 16
    #pragma unroll 1
    for (int it = 0; it < NIT; it++) {
        if (it < NIT - 1) { CPA_WAIT1(); } else { CPA_WAIT0(); }
        __syncthreads();
        if (it + 2 < NIT) {
            ISSUE_G(it + 2, (it + 2) % 3);
            CPA_COMMIT();
        }

        const uint32_t cSb = sb + ((it % 3) * GSTAGE) * 4;

        #pragma unroll
        for (int kk = 0; kk < 4; kk++) {
            uint32_t a[2][4], b[8][2];
            #pragma unroll
            for (int mi = 0; mi < 2; mi++)
                ldm_x4(a[mi], cSb + aRB[mi] + jAo[kk]);
            #pragma unroll
            for (int p = 0; p < 4; p++) {
                uint32_t r[4];
                ldm_x4(r, cSb + bRB[p] + jBo[kk]);
                b[2 * p][0]     = r[0]; b[2 * p][1]     = r[1];
                b[2 * p + 1][0] = r[2]; b[2 * p + 1][1] = r[3];
            }
            #pragma unroll
            for (int mi = 0; mi < 2; mi++)
                #pragma unroll
                for (int ni = 0; ni < 8; ni++)
                    mma_fp16(acc[mi][ni], a[mi], b[ni]);
        }
    }

    if (MODE == 0) {
        uint32_t* Yh = (uint32_t*)Yv;
        if (z < 2) {
            // Q/K: RoPE + permuted layout for flash (UNCHANGED consumer)
            const int nh = (n0 + wn) >> 6;
            const float qsc = (z == 0) ? (0.125f * LOG2E) : 1.0f;
            #pragma unroll
            for (int mi = 0; mi < 2; mi++) {
                #pragma unroll
                for (int half = 0; half < 2; half++) {
                    const int row = m0 + wm + 16 * mi + g + 8 * half;
                    const int k0  = 2 * half;
                    const int b_  = row >> 11;
                    const int s   = row & (SS - 1);
                    const int key = row & 3;
                    const size_t ob = ((size_t)(b_ * NHH + nh) * SS + s) * 32;
                    int p = pos_ids[b_ * SS + s];
                    p = min(max(p, 0), SS - 1);
                    const float2* tb = tab + p * 32;
                    #pragma unroll
                    for (int ni = 0; ni < 4; ni++) {
                        const int i0 = 8 * ni + 2 * tg;
                        const float2 t0 = tb[i0];
                        const float2 t1 = tb[i0 + 1];
                        const float lo0 = acc[mi][ni][k0],     lo1 = acc[mi][ni][k0 + 1];
                        const float hi0 = acc[mi][ni + 4][k0], hi1 = acc[mi][ni + 4][k0 + 1];
                        const float nl0 = (lo0 * t0.x - hi0 * t0.y) * qsc;
                        const float nl1 = (lo1 * t1.x - hi1 * t1.y) * qsc;
                        const float nh0 = (hi0 * t0.x + lo0 * t0.y) * qsc;
                        const float nh1 = (hi1 * t1.x + lo1 * t1.y) * qsc;
                        const int c1 = 4 * ni + tg;
                        const int c2 = 16 + 4 * ni + tg;
                        Yh[ob + pcol(c1, key)] = fpack(nl0, nl1);
                        Yh[ob + pcol(c2, key)] = fpack(nh0, nh1);
                    }
                }
            }
        } else {
            // V: register-only shuffle transpose -> Vh (UNCHANGED)
            const int b_    = m0 >> 11;
            const int sbase = (m0 & (SS - 1)) >> 1;
            const int e     = g >> 1;
            const int dpar  = g & 1;
            const bool geven = (dpar == 0);
            #pragma unroll
            for (int mi = 0; mi < 2; mi++) {
                #pragma unroll
                for (int half = 0; half < 2; half++) {
                    const int k0  = 2 * half;
                    const int Wp  = wm + 16 * mi + 8 * half;
                    const int spl = (Wp >> 1) + e;
                    const int c7  = spl & 7;
                    const int spp = (spl & ~7) | ((c7 & 3) << 1) | (c7 >> 2);
                    #pragma unroll
                    for (int ni = 0; ni < 8; ni++) {
                        const uint32_t pk = fpack(acc[mi][ni][k0], acc[mi][ni][k0 + 1]);
                        const uint32_t q  = __shfl_xor_sync(0xffffffffu, pk, 4);
                        const uint32_t lo = geven ? pk : q;
                        const uint32_t hi = geven ? q  : pk;
                        const uint32_t out = __byte_perm(lo, hi, dpar ? 0x7632 : 0x5410);
                        const int dcol = wn + 8 * ni + 2 * tg + dpar;
                        const int nh   = (n0 + dcol) >> 6;
                        const int d    = dcol & 63;
                        Yh[((size_t)(b_ * NHH + nh) * HDD + d) * (SS / 2) + sbase + spp] = out;
                    }
                }
            }
        }
    } else {
        float* Y = (float*)Yv;
        #pragma unroll
        for (int mi = 0; mi < 2; mi++) {
            #pragma unroll
            for (int ni = 0; ni < 8; ni++) {
                const int row = m0 + wm + 16 * mi + g;
                const int col = n0 + wn + 8 * ni + 2 * tg;
                *(float2*)&Y[(size_t)row * HH + col] =
                    make_float2(acc[mi][ni][0], acc[mi][ni][1]);
                *(float2*)&Y[(size_t)(row + 8) * HH + col] =
                    make_float2(acc[mi][ni][2], acc[mi][ni][3]);
            }
        }
    }
    #undef ISSUE_G
}

// ---------------- flash attention: fp16 MMA, paired-diagonal balance --------
// Inner loop identical to R16. Only the AOh epilogue map changed (canonical).
#define FQ 128
#define FK 64
#define VSTR 36
#define SQ_OFF 0
#define SK_OFF (FQ * 32)                 // 4096
#define SV_OFF (FK * 32)                 // 2048
#define STG_SZ (FK * 32 + FK * VSTR)     // 4352 u32
#define NQT (SS / FQ)                    // 16
static const int FLASH_SMEM = (FQ * 32 + 3 * STG_SZ) * (int)sizeof(uint32_t);  // 68608

__global__ void __launch_bounds__(256, 2) flash_fp16(const uint32_t* __restrict__ Qh,
                                                     const uint32_t* __restrict__ Kh,
                                                     const uint32_t* __restrict__ Vh,
                                                     uint32_t* __restrict__ AOh)
{
    extern __shared__ uint32_t fsm[];
    const uint32_t sb = smem_u32(fsm);

    const int tid  = threadIdx.x;
    const int w    = tid >> 5;
    const int lane = tid & 31;
    const int g    = lane >> 2;
    const int tg   = lane & 3;
    const int gk   = (g & 3) << 3;
    const int bh   = blockIdx.y;

    const uint32_t* ksrc = Kh + (size_t)bh * SS * 32;
    const uint32_t* vsrc = Vh + (size_t)bh * HDD * (SS / 2);
    const uint32_t* Qs = fsm;
    const int rloc0 = w * 16 + g;
    const int b_ = bh >> 4, nh = bh & 15;

    #define ISSUE_KV(KT, STG)                                                     \
        {                                                                         \
            _Pragma("unroll")                                                     \
            for (int i = 0; i < 2; i++) {                                         \
                const int c = tid + i * 256;                                      \
                const int row = c >> 3, j = c & 7;                                \
                CPA16(sb + (SK_OFF + (STG) * STG_SZ + row * 32 + j * 4) * 4,      \
                      ksrc + ((size_t)(KT) * FK + row) * 32 + j * 4);             \
            }                                                                     \
            _Pragma("unroll")                                                     \
            for (int i = 0; i < 2; i++) {                                         \
                const int c = tid + i * 256;                                      \
                const int d = c >> 3, j = c & 7;                                  \
                CPA16(sb + (SK_OFF + (STG) * STG_SZ + SV_OFF + d * VSTR + j * 4) * 4, \
                      vsrc + (size_t)d * (SS / 2) + (KT) * 32 + j * 4);           \
            }                                                                     \
        }

    #pragma unroll 1
    for (int hv = 0; hv < 2; hv++) {
        const int qt = hv ? (int)blockIdx.x : (NQT - 1 - (int)blockIdx.x);
        const int q0 = qt * FQ;
        const uint32_t* qsrc = Qh + ((size_t)bh * SS + q0) * 32;
        const int nt = 2 * qt + 2;

        if (hv) __syncthreads();

        #pragma unroll
        for (int i = 0; i < 4; i++) {
            const int c = tid + i * 256;
            const int row = c >> 3, j = c & 7;
            CPA16(sb + (SQ_OFF + row * 32 + j * 4) * 4, qsrc + (size_t)row * 32 + j * 4);
        }
        ISSUE_KV(0, 0);
        CPA_COMMIT();
        if (nt > 1) { ISSUE_KV(1, 1); CPA_COMMIT(); }

        float m0r = -1e30f, m1r = -1e30f, l0 = 0.f, l1 = 0.f;
        float acc[8][4];
        #pragma unroll
        for (int ni = 0; ni < 8; ni++)
            #pragma unroll
            for (int r = 0; r < 4; r++) acc[ni][r] = 0.f;

        const int row0 = q0 + rloc0;
        const int row1 = row0 + 8;

        #pragma unroll 1
        for (int kt = 0; kt < nt; kt++) {
            if (kt + 1 < nt) { CPA_WAIT1(); } else { CPA_WAIT0(); }
            __syncthreads();
            if (kt + 2 < nt) { ISSUE_KV(kt + 2, (kt + 2) % 3); CPA_COMMIT(); }

            const uint32_t* Ks = fsm + SK_OFF + (kt % 3) * STG_SZ;
            const uint32_t* Vs = Ks + SV_OFF;
            const int k0 = kt * FK;

            float sc[8][4];
            #pragma unroll
            for (int ni = 0; ni < 8; ni++)
                #pragma unroll
                for (int r = 0; r < 4; r++) sc[ni][r] = 0.f;

            #pragma unroll
            for (int kk = 0; kk < 4; kk++) {
                const int off = ((kk * 8 + 2 * tg) ^ gk);
                uint32_t a[4];
                {
                    uint2 p0 = *(const uint2*)&Qs[rloc0 * 32 + off];
                    uint2 p1 = *(const uint2*)&Qs[(rloc0 + 8) * 32 + off];
                    a[0] = p0.x; a[2] = p0.y;
                    a[1] = p1.x; a[3] = p1.y;
                }
                #pragma unroll
                for (int ni = 0; ni < 8; ni++) {
                    uint2 pb = *(const uint2*)&Ks[(ni * 8 + g) * 32 + off];
                    uint32_t b[2] = {pb.x, pb.y};
                    mma_fp16(sc[ni], a, b);
                }
            }

            if (kt >= 2 * qt) {
                #pragma unroll
                for (int ni = 0; ni < 8; ni++) {
                    const int c = k0 + ni * 8 + 2 * tg;
                    if (c     > row0) sc[ni][0] = -1e30f;
                    if (c + 1 > row0) sc[ni][1] = -1e30f;
                    if (c     > row1) sc[ni][2] = -1e30f;
                    if (c + 1 > row1) sc[ni][3] = -1e30f;
                }
            }

            float mx0 = -1e30f, mx1 = -1e30f;
            #pragma unroll
            for (int ni = 0; ni < 8; ni++) {
                mx0 = fmaxf(mx0, fmaxf(sc[ni][0], sc[ni][1]));
                mx1 = fmaxf(mx1, fmaxf(sc[ni][2], sc[ni][3]));
            }
            #pragma unroll
            for (int off = 1; off < 4; off <<= 1) {
                mx0 = fmaxf(mx0, __shfl_xor_sync(0xffffffffu, mx0, off));
                mx1 = fmaxf(mx1, __shfl_xor_sync(0xffffffffu, mx1, off));
            }
            const float mn0 = fmaxf(m0r, mx0);
            const float mn1 = fmaxf(m1r, mx1);
            const float al0 = exp2f(m0r - mn0);
            const float al1 = exp2f(m1r - mn1);

            #pragma unroll
            for (int ni = 0; ni < 8; ni++) {
                acc[ni][0] *= al0; acc[ni][1] *= al0;
                acc[ni][2] *= al1; acc[ni][3] *= al1;
            }

            float s0 = 0.f, s1 = 0.f;
            #pragma unroll
            for (int kk = 0; kk < 4; kk++) {
                uint32_t a[4];
                #pragma unroll
                for (int u = 0; u < 2; u++) {
                    const int nj = 2 * kk + u;
                    sc[nj][0] = exp2f(sc[nj][0] - mn0);
                    sc[nj][1] = exp2f(sc[nj][1] - mn0);
                    sc[nj][2] = exp2f(sc[nj][2] - mn1);
                    sc[nj][3] = exp2f(sc[nj][3] - mn1);
                    s0 += sc[nj][0] + sc[nj][1];
                    s1 += sc[nj][2] + sc[nj][3];
                    a[2 * u]     = fpack(sc[nj][0], sc[nj][1]);
                    a[2 * u + 1] = fpack(sc[nj][2], sc[nj][3]);
                }
                const int kc = kk * 8;
                #pragma unroll
                for (int ni = 0; ni < 8; ni++) {
                    uint2 pv = *(const uint2*)&Vs[(ni * 8 + g) * VSTR + kc + 2 * tg];
                    uint32_t b[2] = {pv.x, pv.y};
                    mma_fp16(acc[ni], a, b);
                }
            }

            #pragma unroll
            for (int off = 1; off < 4; off <<= 1) {
                s0 += __shfl_xor_sync(0xffffffffu, s0, off);
                s1 += __shfl_xor_sync(0xffffffffu, s1, off);
            }
            l0 = l0 * al0 + s0;
            l1 = l1 * al1 + s1;
            m0r = mn0; m1r = mn1;
        }

        // epilogue: packed fp16 AO, CANONICAL 3-bit swizzle (out-gemm ldmatrix A)
        const float il0 = 1.f / l0;
        const float il1 = 1.f / l1;
        const int key7 = row0 & 7;           // == row1 & 7 (row1 = row0 + 8)
        #pragma unroll
        for (int ni = 0; ni < 8; ni++) {
            const int cp = nh * 32 + (((ni ^ key7) << 2) | tg);
            AOh[(size_t)(b_ * SS + row0) * HP + cp] =
                fpack(acc[ni][0] * il0, acc[ni][1] * il0);
            AOh[(size_t)(b_ * SS + row1) * HP + cp] =
                fpack(acc[ni][2] * il1, acc[ni][3] * il1);
        }
    }
    #undef ISSUE_KV
}

// ---------------- launcher ---------------------------------------------------
extern "C" void kernel_launch(void* const* d_in, const int* in_sizes, int n_in,
                              void* d_out, int out_size)
{
    (void)in_sizes; (void)n_in; (void)out_size;
    const float* hs = (const float*)d_in[0];
    const float* wq = (const float*)d_in[2];
    const float* wk = (const float*)d_in[3];
    const float* wv = (const float*)d_in[4];
    const float* wo = (const float*)d_in[5];
    const int*  pos = (const int*)d_in[6];
    float* out = (float*)d_out;

    uint32_t *Hh, *Wqh, *Wkh, *Wvh, *Woh, *AOh, *Qh, *Kh, *Vh;
    float2* tab;
    cudaGetSymbolAddress((void**)&Hh,  g_Hh);
    cudaGetSymbolAddress((void**)&Wqh, g_Wqh);
    cudaGetSymbolAddress((void**)&Wkh, g_Wkh);
    cudaGetSymbolAddress((void**)&Wvh, g_Wvh);
    cudaGetSymbolAddress((void**)&Woh, g_Woh);
    cudaGetSymbolAddress((void**)&AOh, g_AOh);
    cudaGetSymbolAddress((void**)&Qh,  g_Qh);
    cudaGetSymbolAddress((void**)&Kh,  g_Kh);
    cudaGetSymbolAddress((void**)&Vh,  g_Vh);
    cudaGetSymbolAddress((void**)&tab, g_tab);

    static bool attr_done = false;
    if (!attr_done) {
        cudaFuncSetAttribute(gemm_v10<0>,
                             cudaFuncAttributeMaxDynamicSharedMemorySize, GEMM_SMEM);
        cudaFuncSetAttribute(gemm_v10<1>,
                             cudaFuncAttributeMaxDynamicSharedMemorySize, GEMM_SMEM);
        cudaFuncSetAttribute(flash_fp16,
                             cudaFuncAttributeMaxDynamicSharedMemorySize, FLASH_SMEM);
        attr_done = true;
    }

    pack_all<<<2048, 256>>>(hs, wq, wk, wv, wo, Hh, Wqh, Wkh, Wvh, Woh, tab);

    gemm_v10<0><<<dim3(HH/GTN, MM/GTM, 3), 256, GEMM_SMEM>>>(
        Hh, Wqh, Wkh, Wvh, Qh, Kh, Vh, tab, pos);

    flash_fp16<<<dim3(NQT/2, BB*NHH), 256, FLASH_SMEM>>>(Qh, Kh, Vh, AOh);

    gemm_v10<1><<<dim3(HH/GTN, MM/GTM, 1), 256, GEMM_SMEM>>>(
        AOh, Woh, Woh, Woh, out, out, out, tab, pos);
}